// round 7
// baseline (speedup 1.0000x reference)
#include <cuda_runtime.h>
#include <math.h>

#define B 16384
#define D 2048
#define E 16
#define C 64

// Scratch (no allocations allowed): routing buckets + counts.
__device__ int g_counts[E];
__device__ int g_bucket[E * B];

__global__ void zero_counts_kernel() {
    if (threadIdx.x < E) g_counts[threadIdx.x] = 0;
}

// ---------------------------------------------------------------------------
// Kernel 1: coarse router GEMM [B,16] + bias + argmax + bucket scatter.
// Block tile: 128 samples x 16 experts, 256 threads, double-buffered staging.
// Thread tile: 4 samples x 2 experts.  (unchanged from R5 — known good)
// ---------------------------------------------------------------------------
#define C1_TM 128
#define C1_TK 32
#define C1_FS (C1_TM + 4)
#define C1_WS (E + 4)
#define NCHUNK (D / C1_TK)

__global__ __launch_bounds__(256) void coarse_kernel(
    const float* __restrict__ features,
    const float* __restrict__ cw,
    const float* __restrict__ cb,
    float* __restrict__ out_coarse,
    float* __restrict__ out_eid)
{
    __shared__ __align__(16) float fs[2][C1_TK][C1_FS];  // [buf][k][sample]
    __shared__ __align__(16) float ws[2][C1_TK][C1_WS];  // [buf][k][expert]

    int tid = threadIdx.x;
    int s0  = blockIdx.x * C1_TM;
    int ty  = tid >> 3;   // 0..31 -> samples ty*4..ty*4+3
    int tx  = tid & 7;    // experts tx and tx+8

    int st_s  = tid >> 3;
    int st_kc = tid & 7;
    int w_e   = tid >> 3;
    int w_kc  = tid & 7;

    float4 pf[4];
    float4 pw;

    float acc0[4] = {0.f, 0.f, 0.f, 0.f};
    float acc1[4] = {0.f, 0.f, 0.f, 0.f};

    {
        int k0 = 0;
        #pragma unroll
        for (int it = 0; it < 4; it++)
            pf[it] = *(const float4*)(features + (size_t)(s0 + st_s + it * 32) * D + k0 + st_kc * 4);
        if (tid < 128)
            pw = *(const float4*)(cw + (size_t)w_e * D + k0 + w_kc * 4);
    }
    #pragma unroll
    for (int it = 0; it < 4; it++) {
        int s = st_s + it * 32;
        fs[0][st_kc * 4 + 0][s] = pf[it].x;
        fs[0][st_kc * 4 + 1][s] = pf[it].y;
        fs[0][st_kc * 4 + 2][s] = pf[it].z;
        fs[0][st_kc * 4 + 3][s] = pf[it].w;
    }
    if (tid < 128) {
        ws[0][w_kc * 4 + 0][w_e] = pw.x;
        ws[0][w_kc * 4 + 1][w_e] = pw.y;
        ws[0][w_kc * 4 + 2][w_e] = pw.z;
        ws[0][w_kc * 4 + 3][w_e] = pw.w;
    }
    __syncthreads();

    for (int chunk = 0; chunk < NCHUNK; chunk++) {
        int cur = chunk & 1;
        int nxt = cur ^ 1;
        if (chunk + 1 < NCHUNK) {
            int k0 = (chunk + 1) * C1_TK;
            #pragma unroll
            for (int it = 0; it < 4; it++)
                pf[it] = *(const float4*)(features + (size_t)(s0 + st_s + it * 32) * D + k0 + st_kc * 4);
            if (tid < 128)
                pw = *(const float4*)(cw + (size_t)w_e * D + k0 + w_kc * 4);
        }

        #pragma unroll 8
        for (int kk = 0; kk < C1_TK; kk++) {
            float4 fa = *(const float4*)&fs[cur][kk][ty * 4];
            float w0 = ws[cur][kk][tx];
            float w1 = ws[cur][kk][tx + 8];
            float f[4] = {fa.x, fa.y, fa.z, fa.w};
            #pragma unroll
            for (int i = 0; i < 4; i++) {
                acc0[i] = fmaf(f[i], w0, acc0[i]);
                acc1[i] = fmaf(f[i], w1, acc1[i]);
            }
        }

        if (chunk + 1 < NCHUNK) {
            #pragma unroll
            for (int it = 0; it < 4; it++) {
                int s = st_s + it * 32;
                fs[nxt][st_kc * 4 + 0][s] = pf[it].x;
                fs[nxt][st_kc * 4 + 1][s] = pf[it].y;
                fs[nxt][st_kc * 4 + 2][s] = pf[it].z;
                fs[nxt][st_kc * 4 + 3][s] = pf[it].w;
            }
            if (tid < 128) {
                ws[nxt][w_kc * 4 + 0][w_e] = pw.x;
                ws[nxt][w_kc * 4 + 1][w_e] = pw.y;
                ws[nxt][w_kc * 4 + 2][w_e] = pw.z;
                ws[nxt][w_kc * 4 + 3][w_e] = pw.w;
            }
            __syncthreads();
        }
    }

    float b0 = cb[tx];
    float b1 = cb[tx + 8];
    #pragma unroll
    for (int i = 0; i < 4; i++) {
        float v0 = acc0[i] + b0;
        float v1 = acc1[i] + b1;
        int gs = s0 + ty * 4 + i;
        out_coarse[(size_t)gs * E + tx]     = v0;
        out_coarse[(size_t)gs * E + tx + 8] = v1;

        float mv = v0; int mi = tx;
        if (v1 > mv) { mv = v1; mi = tx + 8; }
        #pragma unroll
        for (int off = 1; off < 8; off <<= 1) {
            float ov = __shfl_xor_sync(0xffffffffu, mv, off);
            int   oi = __shfl_xor_sync(0xffffffffu, mi, off);
            if (ov > mv || (ov == mv && oi < mi)) { mv = ov; mi = oi; }
        }
        if (tx == 0) {
            out_eid[gs] = (float)mi;
            int pos = atomicAdd(&g_counts[mi], 1);
            g_bucket[mi * B + pos] = gs;
        }
    }
}

// ---------------------------------------------------------------------------
// Kernel 2: per-expert gathered GEMM [cnt_e, 64] + bias + softmax + argmax.
// Block tile: 128 samples x 64 classes, 256 threads, double-buffered staging.
// Thread tile: 8 samples x 4 classes (3 LDS + 32 FFMA per kk).
// Grid (E, 16): covers cnt_e <= 2048 (mean 1024, 33 sigma); ~136 working
// blocks -> single wave on 148 SMs, ~120 cheap early-return blocks.
// ---------------------------------------------------------------------------
#define K2_TM 128
#define K2_TK 32
#define K2_FS (K2_TM + 4)
#define K2_WS (C + 8)

__global__ __launch_bounds__(256) void expert_kernel(
    const float* __restrict__ features,
    const float* __restrict__ ew,
    const float* __restrict__ eb,
    float* __restrict__ out_local,
    float* __restrict__ out_global)
{
    __shared__ __align__(16) float fs[2][K2_TK][K2_FS];  // [buf][k][sample]
    __shared__ __align__(16) float ws[2][K2_TK][K2_WS];  // [buf][k][class]
    __shared__ int ridx[K2_TM];

    int e   = blockIdx.x;
    int cnt = g_counts[e];
    int m0  = blockIdx.y * K2_TM;
    if (m0 >= cnt) return;

    int tid = threadIdx.x;
    if (tid < K2_TM) {
        int r = m0 + tid;
        ridx[tid] = (r < cnt) ? g_bucket[e * B + r] : -1;
    }
    __syncthreads();

    int ty = tid >> 4;   // 0..15 -> samples ty*8..ty*8+7
    int tx = tid & 15;   // classes tx*4..tx*4+3
    const float* wbase = ew + (size_t)e * C * D;

    // staging: features 128 rows x 8 float4 = 1024 tasks (4/thread),
    //          weights  64 rows x 8 float4 =  512 tasks (2/thread)
    int st_r  = tid >> 3;   // 0..31 base row; tasks add it*32
    int st_kc = tid & 7;
    int frow[4];
    #pragma unroll
    for (int it = 0; it < 4; it++) frow[it] = ridx[st_r + it * 32];

    float4 pf[4], pw[2];

    float acc[8][4];
    #pragma unroll
    for (int i = 0; i < 8; i++)
        #pragma unroll
        for (int j = 0; j < 4; j++)
            acc[i][j] = 0.f;

    // --- prologue: load chunk 0 ---
    #pragma unroll
    for (int it = 0; it < 4; it++)
        pf[it] = (frow[it] >= 0)
            ? *(const float4*)(features + (size_t)frow[it] * D + st_kc * 4)
            : make_float4(0.f, 0.f, 0.f, 0.f);
    #pragma unroll
    for (int it = 0; it < 2; it++)
        pw[it] = *(const float4*)(wbase + (size_t)(st_r + it * 32) * D + st_kc * 4);

    #pragma unroll
    for (int it = 0; it < 4; it++) {
        int s = st_r + it * 32;
        fs[0][st_kc * 4 + 0][s] = pf[it].x;
        fs[0][st_kc * 4 + 1][s] = pf[it].y;
        fs[0][st_kc * 4 + 2][s] = pf[it].z;
        fs[0][st_kc * 4 + 3][s] = pf[it].w;
    }
    #pragma unroll
    for (int it = 0; it < 2; it++) {
        int c = st_r + it * 32;
        ws[0][st_kc * 4 + 0][c] = pw[it].x;
        ws[0][st_kc * 4 + 1][c] = pw[it].y;
        ws[0][st_kc * 4 + 2][c] = pw[it].z;
        ws[0][st_kc * 4 + 3][c] = pw[it].w;
    }
    __syncthreads();

    const int NCH = D / K2_TK;
    for (int chunk = 0; chunk < NCH; chunk++) {
        int cur = chunk & 1;
        int nxt = cur ^ 1;
        if (chunk + 1 < NCH) {
            int k0 = (chunk + 1) * K2_TK;
            #pragma unroll
            for (int it = 0; it < 4; it++)
                pf[it] = (frow[it] >= 0)
                    ? *(const float4*)(features + (size_t)frow[it] * D + k0 + st_kc * 4)
                    : make_float4(0.f, 0.f, 0.f, 0.f);
            #pragma unroll
            for (int it = 0; it < 2; it++)
                pw[it] = *(const float4*)(wbase + (size_t)(st_r + it * 32) * D + k0 + st_kc * 4);
        }

        #pragma unroll 8
        for (int kk = 0; kk < K2_TK; kk++) {
            float4 fa0 = *(const float4*)&fs[cur][kk][ty * 8];
            float4 fa1 = *(const float4*)&fs[cur][kk][ty * 8 + 4];
            float4 wb  = *(const float4*)&ws[cur][kk][tx * 4];
            float f[8] = {fa0.x, fa0.y, fa0.z, fa0.w, fa1.x, fa1.y, fa1.z, fa1.w};
            float w[4] = {wb.x, wb.y, wb.z, wb.w};
            #pragma unroll
            for (int i = 0; i < 8; i++)
                #pragma unroll
                for (int j = 0; j < 4; j++)
                    acc[i][j] = fmaf(f[i], w[j], acc[i][j]);
        }

        if (chunk + 1 < NCH) {
            #pragma unroll
            for (int it = 0; it < 4; it++) {
                int s = st_r + it * 32;
                fs[nxt][st_kc * 4 + 0][s] = pf[it].x;
                fs[nxt][st_kc * 4 + 1][s] = pf[it].y;
                fs[nxt][st_kc * 4 + 2][s] = pf[it].z;
                fs[nxt][st_kc * 4 + 3][s] = pf[it].w;
            }
            #pragma unroll
            for (int it = 0; it < 2; it++) {
                int c = st_r + it * 32;
                ws[nxt][st_kc * 4 + 0][c] = pw[it].x;
                ws[nxt][st_kc * 4 + 1][c] = pw[it].y;
                ws[nxt][st_kc * 4 + 2][c] = pw[it].z;
                ws[nxt][st_kc * 4 + 3][c] = pw[it].w;
            }
            __syncthreads();
        }
    }

    // epilogue: bias + softmax + first-occurrence argmax in regs + 16-lane shfl
    float4 b4 = *(const float4*)(eb + e * C + tx * 4);
    float bias[4] = {b4.x, b4.y, b4.z, b4.w};

    #pragma unroll
    for (int i = 0; i < 8; i++) {
        float v[4];
        #pragma unroll
        for (int j = 0; j < 4; j++) v[j] = acc[i][j] + bias[j];

        float mv = v[0]; int mi = tx * 4;
        #pragma unroll
        for (int j = 1; j < 4; j++)
            if (v[j] > mv) { mv = v[j]; mi = tx * 4 + j; }
        #pragma unroll
        for (int off = 1; off < 16; off <<= 1) {
            float ov = __shfl_xor_sync(0xffffffffu, mv, off);
            int   oi = __shfl_xor_sync(0xffffffffu, mi, off);
            if (ov > mv || (ov == mv && oi < mi)) { mv = ov; mi = oi; }
        }

        float sum = 0.f;
        #pragma unroll
        for (int j = 0; j < 4; j++) {
            v[j] = expf(v[j] - mv);
            sum += v[j];
        }
        #pragma unroll
        for (int off = 1; off < 16; off <<= 1)
            sum += __shfl_xor_sync(0xffffffffu, sum, off);
        float inv = 1.0f / sum;

        int row = ridx[ty * 8 + i];
        if (row >= 0) {
            float4 o = make_float4(v[0] * inv, v[1] * inv, v[2] * inv, v[3] * inv);
            *(float4*)(out_local + (size_t)row * C + tx * 4) = o;
            if (tx == 0)
                out_global[row] = (float)(mi + e * C);
        }
    }
}

// ---------------------------------------------------------------------------
// Output layout (reference tuple order, flattened+concatenated, fp32):
//   [0,              B*E)              coarse_output
//   [B*E,            B*E+B)            expert_id (as float)
//   [B*E+B,          B*E+B+B*C)        local_preds
//   [B*E+B+B*C,      B*E+2B+B*C)       global_preds
// ---------------------------------------------------------------------------
extern "C" void kernel_launch(void* const* d_in, const int* in_sizes, int n_in,
                              void* d_out, int out_size) {
    const float* features = (const float*)d_in[0];
    const float* cw       = (const float*)d_in[1];
    const float* cb       = (const float*)d_in[2];
    const float* ew       = (const float*)d_in[3];
    const float* eb       = (const float*)d_in[4];

    float* out        = (float*)d_out;
    float* out_coarse = out;
    float* out_eid    = out + (size_t)B * E;
    float* out_local  = out_eid + B;
    float* out_global = out_local + (size_t)B * C;

    zero_counts_kernel<<<1, 32>>>();
    coarse_kernel<<<B / C1_TM, 256>>>(features, cw, cb, out_coarse, out_eid);
    dim3 g2(E, 16);   // covers cnt_e <= 2048 (mean 1024); x = expert fastest
    expert_kernel<<<g2, 256>>>(features, ew, eb, out_local, out_global);
}

// round 9
// speedup vs baseline: 2.0541x; 2.0541x over previous
#include <cuda_runtime.h>
#include <math.h>

#define B 16384
#define D 2048
#define E 16
#define C 64

#define GRID     296
#define NTHREADS 256

#define TK   32
#define NCH  (D / TK)          // 64 k-chunks

// Phase A (coarse): 256 tiles of 64 samples
#define CT_TM     64
#define N_CTILES  (B / CT_TM)  // 256
#define CFS_S     (CT_TM + 4)  // 68
#define CWS_S     (E + 4)      // 20

// Phase B (expert): tickets over (expert, mtile); covers cnt_e <= 2048 (mean 1024, +33 sigma)
#define ET_TM   64
#define MT_MAX  32
#define NT_EXP  (E * MT_MAX)   // 512
#define EFS_S   (ET_TM + 4)    // 68
#define EWS_S   (C + 8)        // 72

#define SZ_CFS (2 * TK * CFS_S * 4)   // 17408
#define SZ_EFS (2 * TK * EFS_S * 4)   // 17408
#define SZ_EWS (2 * TK * EWS_S * 4)   // 18432
#define SZ_BUF (SZ_EFS + SZ_EWS)      // 35840 (covers coarse 22528 too)

// Persistent scratch (no allocations allowed)
__device__ int g_counts[E];
__device__ int g_bucket[E * B];
__device__ unsigned g_bar;
__device__ unsigned g_ticket;
__device__ unsigned g_done;

__global__ __launch_bounds__(NTHREADS, 2) void moe_kernel(
    const float* __restrict__ features,
    const float* __restrict__ cw,
    const float* __restrict__ cb,
    const float* __restrict__ ew,
    const float* __restrict__ eb,
    float* __restrict__ out_coarse,
    float* __restrict__ out_eid,
    float* __restrict__ out_local,
    float* __restrict__ out_global)
{
    __shared__ __align__(16) char sbuf[SZ_BUF];
    __shared__ int ridx[ET_TM];
    __shared__ int s_cnt[E];
    __shared__ int s_t;

    int tid = threadIdx.x;
    int bid = blockIdx.x;

    // =======================================================================
    // Phase A: coarse router GEMM (64 samples x 16 experts per tile)
    // =======================================================================
    if (bid < N_CTILES) {
        float (*fs)[TK][CFS_S] = (float (*)[TK][CFS_S])sbuf;
        float (*ws)[TK][CWS_S] = (float (*)[TK][CWS_S])(sbuf + SZ_CFS);

        int s0 = bid * CT_TM;
        int ty = tid >> 4;    // 0..15 -> samples ty*4..ty*4+3
        int tx = tid & 15;    // expert
        int st_r  = tid >> 3; // 0..31: feature rows st_r, st_r+32
        int st_kc = tid & 7;
        int w_e   = tid >> 3; // 0..15 (tid<128)
        int w_kc  = tid & 7;

        float4 pf[2], pw;
        float acc[4] = {0.f, 0.f, 0.f, 0.f};

        // prologue: chunk 0
        pf[0] = *(const float4*)(features + (size_t)(s0 + st_r) * D + st_kc * 4);
        pf[1] = *(const float4*)(features + (size_t)(s0 + st_r + 32) * D + st_kc * 4);
        if (tid < 128)
            pw = *(const float4*)(cw + (size_t)w_e * D + w_kc * 4);

        #pragma unroll
        for (int it = 0; it < 2; it++) {
            int s = st_r + it * 32;
            fs[0][st_kc * 4 + 0][s] = pf[it].x;
            fs[0][st_kc * 4 + 1][s] = pf[it].y;
            fs[0][st_kc * 4 + 2][s] = pf[it].z;
            fs[0][st_kc * 4 + 3][s] = pf[it].w;
        }
        if (tid < 128) {
            ws[0][w_kc * 4 + 0][w_e] = pw.x;
            ws[0][w_kc * 4 + 1][w_e] = pw.y;
            ws[0][w_kc * 4 + 2][w_e] = pw.z;
            ws[0][w_kc * 4 + 3][w_e] = pw.w;
        }
        __syncthreads();

        for (int chunk = 0; chunk < NCH; chunk++) {
            int cur = chunk & 1;
            int nxt = cur ^ 1;
            if (chunk + 1 < NCH) {
                int k0 = (chunk + 1) * TK;
                pf[0] = *(const float4*)(features + (size_t)(s0 + st_r) * D + k0 + st_kc * 4);
                pf[1] = *(const float4*)(features + (size_t)(s0 + st_r + 32) * D + k0 + st_kc * 4);
                if (tid < 128)
                    pw = *(const float4*)(cw + (size_t)w_e * D + k0 + w_kc * 4);
            }

            #pragma unroll 8
            for (int kk = 0; kk < TK; kk++) {
                float4 fa = *(const float4*)&fs[cur][kk][ty * 4];
                float w = ws[cur][kk][tx];
                acc[0] = fmaf(fa.x, w, acc[0]);
                acc[1] = fmaf(fa.y, w, acc[1]);
                acc[2] = fmaf(fa.z, w, acc[2]);
                acc[3] = fmaf(fa.w, w, acc[3]);
            }

            if (chunk + 1 < NCH) {
                #pragma unroll
                for (int it = 0; it < 2; it++) {
                    int s = st_r + it * 32;
                    fs[nxt][st_kc * 4 + 0][s] = pf[it].x;
                    fs[nxt][st_kc * 4 + 1][s] = pf[it].y;
                    fs[nxt][st_kc * 4 + 2][s] = pf[it].z;
                    fs[nxt][st_kc * 4 + 3][s] = pf[it].w;
                }
                if (tid < 128) {
                    ws[nxt][w_kc * 4 + 0][w_e] = pw.x;
                    ws[nxt][w_kc * 4 + 1][w_e] = pw.y;
                    ws[nxt][w_kc * 4 + 2][w_e] = pw.z;
                    ws[nxt][w_kc * 4 + 3][w_e] = pw.w;
                }
                __syncthreads();
            }
        }

        float bias = cb[tx];
        #pragma unroll
        for (int i = 0; i < 4; i++) {
            float v = acc[i] + bias;
            int gs = s0 + ty * 4 + i;
            out_coarse[(size_t)gs * E + tx] = v;

            // first-occurrence argmax across the 16 expert lanes
            float mv = v; int mi = tx;
            #pragma unroll
            for (int off = 1; off < 16; off <<= 1) {
                float ov = __shfl_xor_sync(0xffffffffu, mv, off);
                int   oi = __shfl_xor_sync(0xffffffffu, mi, off);
                if (ov > mv || (ov == mv && oi < mi)) { mv = ov; mi = oi; }
            }
            if (tx == 0) {
                out_eid[gs] = (float)mi;
                int pos = atomicAdd(&g_counts[mi], 1);
                g_bucket[mi * B + pos] = gs;
            }
        }
    }

    // =======================================================================
    // Global software barrier (all 296 blocks resident by construction)
    // =======================================================================
    __syncthreads();
    if (tid == 0) {
        __threadfence();
        atomicAdd(&g_bar, 1u);
        while (*((volatile unsigned*)&g_bar) < GRID) __nanosleep(64);
    }
    __syncthreads();
    __threadfence();

    // =======================================================================
    // Phase B: expert GEMM tiles via atomic work ticket
    // =======================================================================
    if (tid < E) s_cnt[tid] = g_counts[tid];

    float (*fs)[TK][EFS_S] = (float (*)[TK][EFS_S])sbuf;
    float (*ws)[TK][EWS_S] = (float (*)[TK][EWS_S])(sbuf + SZ_EFS);

    for (;;) {
        __syncthreads();
        if (tid == 0) s_t = (int)atomicAdd(&g_ticket, 1u);
        __syncthreads();
        int t = s_t;
        if (t >= NT_EXP) break;

        int e  = t & (E - 1);
        int mt = t >> 4;
        int cnt = s_cnt[e];
        int m0  = mt * ET_TM;
        if (m0 >= cnt) continue;

        if (tid < ET_TM)
            ridx[tid] = (m0 + tid < cnt) ? g_bucket[e * B + m0 + tid] : -1;
        __syncthreads();

        int ty = tid >> 4;   // samples ty*4..ty*4+3
        int tx = tid & 15;   // classes tx*4..tx*4+3
        const float* wbase = ew + (size_t)e * C * D;

        int st_r  = tid >> 3;   // 0..31
        int st_kc = tid & 7;
        int frow0 = ridx[st_r];
        int frow1 = ridx[st_r + 32];

        float4 pf[2], pw[2];
        float acc[4][4];
        #pragma unroll
        for (int i = 0; i < 4; i++)
            #pragma unroll
            for (int j = 0; j < 4; j++)
                acc[i][j] = 0.f;

        // prologue: chunk 0
        pf[0] = (frow0 >= 0) ? *(const float4*)(features + (size_t)frow0 * D + st_kc * 4)
                             : make_float4(0.f, 0.f, 0.f, 0.f);
        pf[1] = (frow1 >= 0) ? *(const float4*)(features + (size_t)frow1 * D + st_kc * 4)
                             : make_float4(0.f, 0.f, 0.f, 0.f);
        pw[0] = *(const float4*)(wbase + (size_t)st_r * D + st_kc * 4);
        pw[1] = *(const float4*)(wbase + (size_t)(st_r + 32) * D + st_kc * 4);

        #pragma unroll
        for (int it = 0; it < 2; it++) {
            int s = st_r + it * 32;
            fs[0][st_kc * 4 + 0][s] = pf[it].x;
            fs[0][st_kc * 4 + 1][s] = pf[it].y;
            fs[0][st_kc * 4 + 2][s] = pf[it].z;
            fs[0][st_kc * 4 + 3][s] = pf[it].w;
            ws[0][st_kc * 4 + 0][s] = pw[it].x;
            ws[0][st_kc * 4 + 1][s] = pw[it].y;
            ws[0][st_kc * 4 + 2][s] = pw[it].z;
            ws[0][st_kc * 4 + 3][s] = pw[it].w;
        }
        __syncthreads();

        for (int chunk = 0; chunk < NCH; chunk++) {
            int cur = chunk & 1;
            int nxt = cur ^ 1;
            if (chunk + 1 < NCH) {
                int k0 = (chunk + 1) * TK;
                pf[0] = (frow0 >= 0) ? *(const float4*)(features + (size_t)frow0 * D + k0 + st_kc * 4)
                                     : make_float4(0.f, 0.f, 0.f, 0.f);
                pf[1] = (frow1 >= 0) ? *(const float4*)(features + (size_t)frow1 * D + k0 + st_kc * 4)
                                     : make_float4(0.f, 0.f, 0.f, 0.f);
                pw[0] = *(const float4*)(wbase + (size_t)st_r * D + k0 + st_kc * 4);
                pw[1] = *(const float4*)(wbase + (size_t)(st_r + 32) * D + k0 + st_kc * 4);
            }

            #pragma unroll 8
            for (int kk = 0; kk < TK; kk++) {
                float4 fa = *(const float4*)&fs[cur][kk][ty * 4];
                float4 wb = *(const float4*)&ws[cur][kk][tx * 4];
                float f[4] = {fa.x, fa.y, fa.z, fa.w};
                float w[4] = {wb.x, wb.y, wb.z, wb.w};
                #pragma unroll
                for (int i = 0; i < 4; i++)
                    #pragma unroll
                    for (int j = 0; j < 4; j++)
                        acc[i][j] = fmaf(f[i], w[j], acc[i][j]);
            }

            if (chunk + 1 < NCH) {
                #pragma unroll
                for (int it = 0; it < 2; it++) {
                    int s = st_r + it * 32;
                    fs[nxt][st_kc * 4 + 0][s] = pf[it].x;
                    fs[nxt][st_kc * 4 + 1][s] = pf[it].y;
                    fs[nxt][st_kc * 4 + 2][s] = pf[it].z;
                    fs[nxt][st_kc * 4 + 3][s] = pf[it].w;
                    ws[nxt][st_kc * 4 + 0][s] = pw[it].x;
                    ws[nxt][st_kc * 4 + 1][s] = pw[it].y;
                    ws[nxt][st_kc * 4 + 2][s] = pw[it].z;
                    ws[nxt][st_kc * 4 + 3][s] = pw[it].w;
                }
                __syncthreads();
            }
        }

        // epilogue: bias + softmax + first-occurrence argmax (regs + 16-lane shfl)
        float4 b4 = *(const float4*)(eb + e * C + tx * 4);
        float bias[4] = {b4.x, b4.y, b4.z, b4.w};

        #pragma unroll
        for (int i = 0; i < 4; i++) {
            float v[4];
            #pragma unroll
            for (int j = 0; j < 4; j++) v[j] = acc[i][j] + bias[j];

            float mv = v[0]; int mi = tx * 4;
            #pragma unroll
            for (int j = 1; j < 4; j++)
                if (v[j] > mv) { mv = v[j]; mi = tx * 4 + j; }
            #pragma unroll
            for (int off = 1; off < 16; off <<= 1) {
                float ov = __shfl_xor_sync(0xffffffffu, mv, off);
                int   oi = __shfl_xor_sync(0xffffffffu, mi, off);
                if (ov > mv || (ov == mv && oi < mi)) { mv = ov; mi = oi; }
            }

            float sum = 0.f;
            #pragma unroll
            for (int j = 0; j < 4; j++) {
                v[j] = expf(v[j] - mv);
                sum += v[j];
            }
            #pragma unroll
            for (int off = 1; off < 16; off <<= 1)
                sum += __shfl_xor_sync(0xffffffffu, sum, off);
            float inv = 1.0f / sum;

            int row = ridx[ty * 4 + i];
            if (row >= 0) {
                float4 o = make_float4(v[0] * inv, v[1] * inv, v[2] * inv, v[3] * inv);
                *(float4*)(out_local + (size_t)row * C + tx * 4) = o;
                if (tx == 0)
                    out_global[row] = (float)(mi + e * C);
            }
        }
    }

    // =======================================================================
    // Reset persistent counters for the next graph replay. The last block to
    // arrive resets; safe because every block has already finished all reads.
    // =======================================================================
    __syncthreads();
    if (tid == 0) {
        unsigned d = atomicAdd(&g_done, 1u);
        if (d == GRID - 1) {
            #pragma unroll
            for (int i = 0; i < E; i++) g_counts[i] = 0;
            g_ticket = 0;
            g_bar = 0;
            __threadfence();
            g_done = 0;
        }
    }
}

// ---------------------------------------------------------------------------
// Output layout (reference tuple order, flattened+concatenated, fp32):
//   [0,              B*E)              coarse_output
//   [B*E,            B*E+B)            expert_id (as float)
//   [B*E+B,          B*E+B+B*C)        local_preds
//   [B*E+B+B*C,      B*E+2B+B*C)       global_preds
// ---------------------------------------------------------------------------
extern "C" void kernel_launch(void* const* d_in, const int* in_sizes, int n_in,
                              void* d_out, int out_size) {
    const float* features = (const float*)d_in[0];
    const float* cw       = (const float*)d_in[1];
    const float* cb       = (const float*)d_in[2];
    const float* ew       = (const float*)d_in[3];
    const float* eb       = (const float*)d_in[4];

    float* out        = (float*)d_out;
    float* out_coarse = out;
    float* out_eid    = out + (size_t)B * E;
    float* out_local  = out_eid + B;
    float* out_global = out_local + (size_t)B * C;

    moe_kernel<<<GRID, NTHREADS>>>(features, cw, cb, ew, eb,
                                   out_coarse, out_eid, out_local, out_global);
}

// round 10
// speedup vs baseline: 2.0569x; 1.0014x over previous
#include <cuda_runtime.h>
#include <math.h>

#define B 16384
#define D 2048
#define E 16
#define C 64

#define GRID     296
#define NTHREADS 256

#define TK   32
#define NCH  (D / TK)          // 64 k-chunks

// Phase A (coarse): 256 tiles of 64 samples
#define CT_TM     64
#define N_CTILES  (B / CT_TM)  // 256
#define CFS_S     (CT_TM + 4)  // 68
#define CWS_S     (E + 4)      // 20

// Phase B (expert): tickets over (expert, mtile); covers cnt_e <= 2048 (mean 1024, +33 sigma)
#define ET_TM   64
#define MT_MAX  32
#define NT_EXP  (E * MT_MAX)   // 512
#define EFS_S   (ET_TM + 4)    // 68
#define EWS_S   (C + 8)        // 72

#define SZ_CFS (2 * TK * CFS_S * 4)   // 17408
#define SZ_EFS (2 * TK * EFS_S * 4)   // 17408
#define SZ_EWS (2 * TK * EWS_S * 4)   // 18432
#define SZ_BUF (SZ_EFS + SZ_EWS)      // 35840 (covers coarse 22528 too)

// Persistent scratch (no allocations allowed)
__device__ int g_counts[E];
__device__ int g_bucket[E * B];
__device__ unsigned g_bar;
__device__ unsigned g_ticket;
__device__ unsigned g_done;

__global__ __launch_bounds__(NTHREADS, 2) void moe_kernel(
    const float* __restrict__ features,
    const float* __restrict__ cw,
    const float* __restrict__ cb,
    const float* __restrict__ ew,
    const float* __restrict__ eb,
    float* __restrict__ out_coarse,
    float* __restrict__ out_eid,
    float* __restrict__ out_local,
    float* __restrict__ out_global)
{
    __shared__ __align__(16) char sbuf[SZ_BUF];
    __shared__ int ridx[ET_TM];
    __shared__ int s_cnt[E];
    __shared__ int s_t;

    int tid = threadIdx.x;
    int bid = blockIdx.x;

    // =======================================================================
    // Phase A: coarse router GEMM (64 samples x 16 experts per tile)
    // =======================================================================
    if (bid < N_CTILES) {
        float (*fs)[TK][CFS_S] = (float (*)[TK][CFS_S])sbuf;
        float (*ws)[TK][CWS_S] = (float (*)[TK][CWS_S])(sbuf + SZ_CFS);

        int s0 = bid * CT_TM;
        int ty = tid >> 4;    // 0..15 -> samples ty*4..ty*4+3
        int tx = tid & 15;    // expert
        int st_r  = tid >> 3; // 0..31: feature rows st_r, st_r+32
        int st_kc = tid & 7;
        int w_e   = tid >> 3; // 0..15 (tid<128)
        int w_kc  = tid & 7;

        float4 pf[2], pw;
        float acc[4] = {0.f, 0.f, 0.f, 0.f};

        // prologue: chunk 0
        pf[0] = *(const float4*)(features + (size_t)(s0 + st_r) * D + st_kc * 4);
        pf[1] = *(const float4*)(features + (size_t)(s0 + st_r + 32) * D + st_kc * 4);
        if (tid < 128)
            pw = *(const float4*)(cw + (size_t)w_e * D + w_kc * 4);

        #pragma unroll
        for (int it = 0; it < 2; it++) {
            int s = st_r + it * 32;
            fs[0][st_kc * 4 + 0][s] = pf[it].x;
            fs[0][st_kc * 4 + 1][s] = pf[it].y;
            fs[0][st_kc * 4 + 2][s] = pf[it].z;
            fs[0][st_kc * 4 + 3][s] = pf[it].w;
        }
        if (tid < 128) {
            ws[0][w_kc * 4 + 0][w_e] = pw.x;
            ws[0][w_kc * 4 + 1][w_e] = pw.y;
            ws[0][w_kc * 4 + 2][w_e] = pw.z;
            ws[0][w_kc * 4 + 3][w_e] = pw.w;
        }
        __syncthreads();

        for (int chunk = 0; chunk < NCH; chunk++) {
            int cur = chunk & 1;
            int nxt = cur ^ 1;
            if (chunk + 1 < NCH) {
                int k0 = (chunk + 1) * TK;
                pf[0] = *(const float4*)(features + (size_t)(s0 + st_r) * D + k0 + st_kc * 4);
                pf[1] = *(const float4*)(features + (size_t)(s0 + st_r + 32) * D + k0 + st_kc * 4);
                if (tid < 128)
                    pw = *(const float4*)(cw + (size_t)w_e * D + k0 + w_kc * 4);
            }

            #pragma unroll 8
            for (int kk = 0; kk < TK; kk++) {
                float4 fa = *(const float4*)&fs[cur][kk][ty * 4];
                float w = ws[cur][kk][tx];
                acc[0] = fmaf(fa.x, w, acc[0]);
                acc[1] = fmaf(fa.y, w, acc[1]);
                acc[2] = fmaf(fa.z, w, acc[2]);
                acc[3] = fmaf(fa.w, w, acc[3]);
            }

            if (chunk + 1 < NCH) {
                #pragma unroll
                for (int it = 0; it < 2; it++) {
                    int s = st_r + it * 32;
                    fs[nxt][st_kc * 4 + 0][s] = pf[it].x;
                    fs[nxt][st_kc * 4 + 1][s] = pf[it].y;
                    fs[nxt][st_kc * 4 + 2][s] = pf[it].z;
                    fs[nxt][st_kc * 4 + 3][s] = pf[it].w;
                }
                if (tid < 128) {
                    ws[nxt][w_kc * 4 + 0][w_e] = pw.x;
                    ws[nxt][w_kc * 4 + 1][w_e] = pw.y;
                    ws[nxt][w_kc * 4 + 2][w_e] = pw.z;
                    ws[nxt][w_kc * 4 + 3][w_e] = pw.w;
                }
                __syncthreads();
            }
        }

        float bias = cb[tx];
        #pragma unroll
        for (int i = 0; i < 4; i++) {
            float v = acc[i] + bias;
            int gs = s0 + ty * 4 + i;
            out_coarse[(size_t)gs * E + tx] = v;

            // first-occurrence argmax across the 16 expert lanes
            float mv = v; int mi = tx;
            #pragma unroll
            for (int off = 1; off < 16; off <<= 1) {
                float ov = __shfl_xor_sync(0xffffffffu, mv, off);
                int   oi = __shfl_xor_sync(0xffffffffu, mi, off);
                if (ov > mv || (ov == mv && oi < mi)) { mv = ov; mi = oi; }
            }
            if (tx == 0) {
                out_eid[gs] = (float)mi;
                int pos = atomicAdd(&g_counts[mi], 1);
                g_bucket[mi * B + pos] = gs;
            }
        }
    }

    // =======================================================================
    // Global software barrier (all 296 blocks resident by construction)
    // =======================================================================
    __syncthreads();
    if (tid == 0) {
        __threadfence();
        atomicAdd(&g_bar, 1u);
        while (*((volatile unsigned*)&g_bar) < GRID) __nanosleep(64);
    }
    __syncthreads();
    __threadfence();

    // =======================================================================
    // Phase B: expert GEMM tiles via atomic work ticket
    // =======================================================================
    if (tid < E) s_cnt[tid] = g_counts[tid];

    float (*fs)[TK][EFS_S] = (float (*)[TK][EFS_S])sbuf;
    float (*ws)[TK][EWS_S] = (float (*)[TK][EWS_S])(sbuf + SZ_EFS);

    for (;;) {
        __syncthreads();
        if (tid == 0) s_t = (int)atomicAdd(&g_ticket, 1u);
        __syncthreads();
        int t = s_t;
        if (t >= NT_EXP) break;

        int e  = t & (E - 1);
        int mt = t >> 4;
        int cnt = s_cnt[e];
        int m0  = mt * ET_TM;
        if (m0 >= cnt) continue;

        if (tid < ET_TM)
            ridx[tid] = (m0 + tid < cnt) ? g_bucket[e * B + m0 + tid] : -1;
        __syncthreads();

        int ty = tid >> 4;   // samples ty*4..ty*4+3
        int tx = tid & 15;   // classes tx*4..tx*4+3
        const float* wbase = ew + (size_t)e * C * D;

        int st_r  = tid >> 3;   // 0..31
        int st_kc = tid & 7;
        int frow0 = ridx[st_r];
        int frow1 = ridx[st_r + 32];

        float4 pf[2], pw[2];
        float acc[4][4];
        #pragma unroll
        for (int i = 0; i < 4; i++)
            #pragma unroll
            for (int j = 0; j < 4; j++)
                acc[i][j] = 0.f;

        // prologue: chunk 0
        pf[0] = (frow0 >= 0) ? *(const float4*)(features + (size_t)frow0 * D + st_kc * 4)
                             : make_float4(0.f, 0.f, 0.f, 0.f);
        pf[1] = (frow1 >= 0) ? *(const float4*)(features + (size_t)frow1 * D + st_kc * 4)
                             : make_float4(0.f, 0.f, 0.f, 0.f);
        pw[0] = *(const float4*)(wbase + (size_t)st_r * D + st_kc * 4);
        pw[1] = *(const float4*)(wbase + (size_t)(st_r + 32) * D + st_kc * 4);

        #pragma unroll
        for (int it = 0; it < 2; it++) {
            int s = st_r + it * 32;
            fs[0][st_kc * 4 + 0][s] = pf[it].x;
            fs[0][st_kc * 4 + 1][s] = pf[it].y;
            fs[0][st_kc * 4 + 2][s] = pf[it].z;
            fs[0][st_kc * 4 + 3][s] = pf[it].w;
            ws[0][st_kc * 4 + 0][s] = pw[it].x;
            ws[0][st_kc * 4 + 1][s] = pw[it].y;
            ws[0][st_kc * 4 + 2][s] = pw[it].z;
            ws[0][st_kc * 4 + 3][s] = pw[it].w;
        }
        __syncthreads();

        for (int chunk = 0; chunk < NCH; chunk++) {
            int cur = chunk & 1;
            int nxt = cur ^ 1;
            if (chunk + 1 < NCH) {
                int k0 = (chunk + 1) * TK;
                pf[0] = (frow0 >= 0) ? *(const float4*)(features + (size_t)frow0 * D + k0 + st_kc * 4)
                                     : make_float4(0.f, 0.f, 0.f, 0.f);
                pf[1] = (frow1 >= 0) ? *(const float4*)(features + (size_t)frow1 * D + k0 + st_kc * 4)
                                     : make_float4(0.f, 0.f, 0.f, 0.f);
                pw[0] = *(const float4*)(wbase + (size_t)st_r * D + k0 + st_kc * 4);
                pw[1] = *(const float4*)(wbase + (size_t)(st_r + 32) * D + k0 + st_kc * 4);
            }

            #pragma unroll 8
            for (int kk = 0; kk < TK; kk++) {
                float4 fa = *(const float4*)&fs[cur][kk][ty * 4];
                float4 wb = *(const float4*)&ws[cur][kk][tx * 4];
                float f[4] = {fa.x, fa.y, fa.z, fa.w};
                float w[4] = {wb.x, wb.y, wb.z, wb.w};
                #pragma unroll
                for (int i = 0; i < 4; i++)
                    #pragma unroll
                    for (int j = 0; j < 4; j++)
                        acc[i][j] = fmaf(f[i], w[j], acc[i][j]);
            }

            if (chunk + 1 < NCH) {
                #pragma unroll
                for (int it = 0; it < 2; it++) {
                    int s = st_r + it * 32;
                    fs[nxt][st_kc * 4 + 0][s] = pf[it].x;
                    fs[nxt][st_kc * 4 + 1][s] = pf[it].y;
                    fs[nxt][st_kc * 4 + 2][s] = pf[it].z;
                    fs[nxt][st_kc * 4 + 3][s] = pf[it].w;
                    ws[nxt][st_kc * 4 + 0][s] = pw[it].x;
                    ws[nxt][st_kc * 4 + 1][s] = pw[it].y;
                    ws[nxt][st_kc * 4 + 2][s] = pw[it].z;
                    ws[nxt][st_kc * 4 + 3][s] = pw[it].w;
                }
                __syncthreads();
            }
        }

        // epilogue: bias + softmax + first-occurrence argmax (regs + 16-lane shfl)
        float4 b4 = *(const float4*)(eb + e * C + tx * 4);
        float bias[4] = {b4.x, b4.y, b4.z, b4.w};

        #pragma unroll
        for (int i = 0; i < 4; i++) {
            float v[4];
            #pragma unroll
            for (int j = 0; j < 4; j++) v[j] = acc[i][j] + bias[j];

            float mv = v[0]; int mi = tx * 4;
            #pragma unroll
            for (int j = 1; j < 4; j++)
                if (v[j] > mv) { mv = v[j]; mi = tx * 4 + j; }
            #pragma unroll
            for (int off = 1; off < 16; off <<= 1) {
                float ov = __shfl_xor_sync(0xffffffffu, mv, off);
                int   oi = __shfl_xor_sync(0xffffffffu, mi, off);
                if (ov > mv || (ov == mv && oi < mi)) { mv = ov; mi = oi; }
            }

            float sum = 0.f;
            #pragma unroll
            for (int j = 0; j < 4; j++) {
                v[j] = expf(v[j] - mv);
                sum += v[j];
            }
            #pragma unroll
            for (int off = 1; off < 16; off <<= 1)
                sum += __shfl_xor_sync(0xffffffffu, sum, off);
            float inv = 1.0f / sum;

            int row = ridx[ty * 4 + i];
            if (row >= 0) {
                float4 o = make_float4(v[0] * inv, v[1] * inv, v[2] * inv, v[3] * inv);
                *(float4*)(out_local + (size_t)row * C + tx * 4) = o;
                if (tx == 0)
                    out_global[row] = (float)(mi + e * C);
            }
        }
    }

    // =======================================================================
    // Reset persistent counters for the next graph replay. The last block to
    // arrive resets; safe because every block has already finished all reads.
    // =======================================================================
    __syncthreads();
    if (tid == 0) {
        unsigned d = atomicAdd(&g_done, 1u);
        if (d == GRID - 1) {
            #pragma unroll
            for (int i = 0; i < E; i++) g_counts[i] = 0;
            g_ticket = 0;
            g_bar = 0;
            __threadfence();
            g_done = 0;
        }
    }
}

// ---------------------------------------------------------------------------
// Output layout (reference tuple order, flattened+concatenated, fp32):
//   [0,              B*E)              coarse_output
//   [B*E,            B*E+B)            expert_id (as float)
//   [B*E+B,          B*E+B+B*C)        local_preds
//   [B*E+B+B*C,      B*E+2B+B*C)       global_preds
// ---------------------------------------------------------------------------
extern "C" void kernel_launch(void* const* d_in, const int* in_sizes, int n_in,
                              void* d_out, int out_size) {
    const float* features = (const float*)d_in[0];
    const float* cw       = (const float*)d_in[1];
    const float* cb       = (const float*)d_in[2];
    const float* ew       = (const float*)d_in[3];
    const float* eb       = (const float*)d_in[4];

    float* out        = (float*)d_out;
    float* out_coarse = out;
    float* out_eid    = out + (size_t)B * E;
    float* out_local  = out_eid + B;
    float* out_global = out_local + (size_t)B * C;

    moe_kernel<<<GRID, NTHREADS>>>(features, cw, cb, ew, eb,
                                   out_coarse, out_eid, out_local, out_global);
}

// round 11
// speedup vs baseline: 2.1709x; 1.0554x over previous
#include <cuda_runtime.h>
#include <math.h>

#define B 16384
#define D 2048
#define E 16
#define C 64

#define GRID     296
#define NTHREADS 256

#define TK   32
#define NCH  (D / TK)          // 64 k-chunks

// Phase A (coarse): 256 tiles of 64 samples
#define CT_TM     64
#define N_CTILES  (B / CT_TM)  // 256

// Phase B (expert): tickets over (expert, mtile)
#define ET_TM   64
#define MT_MAX  32
#define NT_EXP  (E * MT_MAX)   // 512

// Swizzled smem tiles: rows of exactly 64 floats (ws coarse: 16).
// float4-chunk swizzle: c4' = c4 ^ ((krow>>2)&7)  -> staging STS conflict-free,
// compute LDS optimal. All indices become compile-time constants under full unroll.
#define SZ_T64  (2 * TK * 64 * 4)     // 16384 bytes per [2][32][64] tile
#define SZ_T16  (2 * TK * 16 * 4)     // 4096  bytes per [2][32][16] tile
#define SZ_BUF  (SZ_T64 + SZ_T64)     // expert fs+ws = 32768 (covers coarse 20480)

// float index helpers (col = scalar column, c4 = column/4)
__device__ __forceinline__ int idx64(int krow, int col) {
    return krow * 64 + ((((col) >> 2) ^ ((krow >> 2) & 7)) << 2) + ((col) & 3);
}
__device__ __forceinline__ int idx64v(int krow, int c4) {   // float4 base
    return krow * 64 + (((c4) ^ ((krow >> 2) & 7)) << 2);
}
__device__ __forceinline__ int idx16(int krow, int col) {
    return krow * 16 + ((((col) >> 2) ^ ((krow >> 2) & 3)) << 2) + ((col) & 3);
}

// Persistent scratch (no allocations allowed)
__device__ int g_counts[E];
__device__ int g_bucket[E * B];
__device__ unsigned g_bar;
__device__ unsigned g_ticket;
__device__ unsigned g_done;

__global__ __launch_bounds__(NTHREADS, 2) void moe_kernel(
    const float* __restrict__ features,
    const float* __restrict__ cw,
    const float* __restrict__ cb,
    const float* __restrict__ ew,
    const float* __restrict__ eb,
    float* __restrict__ out_coarse,
    float* __restrict__ out_eid,
    float* __restrict__ out_local,
    float* __restrict__ out_global)
{
    __shared__ __align__(16) float sbuf[SZ_BUF / 4];
    __shared__ int ridx[ET_TM];
    __shared__ int s_cnt[E];
    __shared__ int s_t;

    int tid = threadIdx.x;
    int bid = blockIdx.x;

    // =======================================================================
    // Phase A: coarse router GEMM (64 samples x 16 experts per tile)
    // fs: [2][32][64] swizzled at sbuf, ws: [2][32][16] swizzled after it
    // =======================================================================
    if (bid < N_CTILES) {
        float* fsb = sbuf;
        float* wsb = sbuf + (SZ_T64 / 4);

        int s0 = bid * CT_TM;
        int ty = tid >> 4;    // 0..15 -> samples ty*4..ty*4+3 (c4 = ty)
        int tx = tid & 15;    // expert
        int st_r  = tid >> 3; // 0..31: feature rows st_r, st_r+32
        int st_kc = tid & 7;
        int w_e   = tid >> 3; // 0..15 (tid<128)
        int w_kc  = tid & 7;

        float4 pf[2], pw;
        float acc[4] = {0.f, 0.f, 0.f, 0.f};

        // prologue: chunk 0
        pf[0] = *(const float4*)(features + (size_t)(s0 + st_r) * D + st_kc * 4);
        pf[1] = *(const float4*)(features + (size_t)(s0 + st_r + 32) * D + st_kc * 4);
        if (tid < 128)
            pw = *(const float4*)(cw + (size_t)w_e * D + w_kc * 4);

        #pragma unroll
        for (int it = 0; it < 2; it++) {
            int s = st_r + it * 32;
            float v[4] = {pf[it].x, pf[it].y, pf[it].z, pf[it].w};
            #pragma unroll
            for (int j = 0; j < 4; j++)
                fsb[0 * (TK * 64) + idx64(st_kc * 4 + j, s)] = v[j];
        }
        if (tid < 128) {
            float v[4] = {pw.x, pw.y, pw.z, pw.w};
            #pragma unroll
            for (int j = 0; j < 4; j++)
                wsb[0 * (TK * 16) + idx16(w_kc * 4 + j, w_e)] = v[j];
        }
        __syncthreads();

        for (int chunk = 0; chunk < NCH; chunk++) {
            int cur = chunk & 1;
            int nxt = cur ^ 1;
            if (chunk + 1 < NCH) {
                int k0 = (chunk + 1) * TK;
                pf[0] = *(const float4*)(features + (size_t)(s0 + st_r) * D + k0 + st_kc * 4);
                pf[1] = *(const float4*)(features + (size_t)(s0 + st_r + 32) * D + k0 + st_kc * 4);
                if (tid < 128)
                    pw = *(const float4*)(cw + (size_t)w_e * D + k0 + w_kc * 4);
            }

            const float* fsc = fsb + cur * (TK * 64);
            const float* wsc = wsb + cur * (TK * 16);
            #pragma unroll
            for (int kk = 0; kk < TK; kk++) {
                float4 fa = *(const float4*)&fsc[idx64v(kk, ty)];
                float w = wsc[idx16(kk, tx)];
                acc[0] = fmaf(fa.x, w, acc[0]);
                acc[1] = fmaf(fa.y, w, acc[1]);
                acc[2] = fmaf(fa.z, w, acc[2]);
                acc[3] = fmaf(fa.w, w, acc[3]);
            }

            if (chunk + 1 < NCH) {
                #pragma unroll
                for (int it = 0; it < 2; it++) {
                    int s = st_r + it * 32;
                    float v[4] = {pf[it].x, pf[it].y, pf[it].z, pf[it].w};
                    #pragma unroll
                    for (int j = 0; j < 4; j++)
                        fsb[nxt * (TK * 64) + idx64(st_kc * 4 + j, s)] = v[j];
                }
                if (tid < 128) {
                    float v[4] = {pw.x, pw.y, pw.z, pw.w};
                    #pragma unroll
                    for (int j = 0; j < 4; j++)
                        wsb[nxt * (TK * 16) + idx16(w_kc * 4 + j, w_e)] = v[j];
                }
                __syncthreads();
            }
        }

        float bias = cb[tx];
        #pragma unroll
        for (int i = 0; i < 4; i++) {
            float v = acc[i] + bias;
            int gs = s0 + ty * 4 + i;
            out_coarse[(size_t)gs * E + tx] = v;

            // first-occurrence argmax across the 16 expert lanes
            float mv = v; int mi = tx;
            #pragma unroll
            for (int off = 1; off < 16; off <<= 1) {
                float ov = __shfl_xor_sync(0xffffffffu, mv, off);
                int   oi = __shfl_xor_sync(0xffffffffu, mi, off);
                if (ov > mv || (ov == mv && oi < mi)) { mv = ov; mi = oi; }
            }
            if (tx == 0) {
                out_eid[gs] = (float)mi;
                int pos = atomicAdd(&g_counts[mi], 1);
                g_bucket[mi * B + pos] = gs;
            }
        }
    }

    // =======================================================================
    // Global software barrier (all 296 blocks resident by construction)
    // =======================================================================
    __syncthreads();
    if (tid == 0) {
        __threadfence();
        atomicAdd(&g_bar, 1u);
        while (*((volatile unsigned*)&g_bar) < GRID) __nanosleep(64);
    }
    __syncthreads();
    __threadfence();

    // =======================================================================
    // Phase B: expert GEMM tiles via atomic work ticket
    // fs: [2][32][64] swizzled, ws: [2][32][64] swizzled
    // =======================================================================
    if (tid < E) s_cnt[tid] = g_counts[tid];

    float* fsb = sbuf;
    float* wsb = sbuf + (SZ_T64 / 4);

    for (;;) {
        __syncthreads();
        if (tid == 0) s_t = (int)atomicAdd(&g_ticket, 1u);
        __syncthreads();
        int t = s_t;
        if (t >= NT_EXP) break;

        int e  = t & (E - 1);
        int mt = t >> 4;
        int cnt = s_cnt[e];
        int m0  = mt * ET_TM;
        if (m0 >= cnt) continue;

        if (tid < ET_TM)
            ridx[tid] = (m0 + tid < cnt) ? g_bucket[e * B + m0 + tid] : -1;
        __syncthreads();

        int ty = tid >> 4;   // samples ty*4..ty*4+3 (c4 = ty)
        int tx = tid & 15;   // classes tx*4..tx*4+3 (c4 = tx)
        const float* wbase = ew + (size_t)e * C * D;

        int st_r  = tid >> 3;   // 0..31
        int st_kc = tid & 7;
        int frow0 = ridx[st_r];
        int frow1 = ridx[st_r + 32];

        float4 pf[2], pw[2];
        float acc[4][4];
        #pragma unroll
        for (int i = 0; i < 4; i++)
            #pragma unroll
            for (int j = 0; j < 4; j++)
                acc[i][j] = 0.f;

        // prologue: chunk 0
        pf[0] = (frow0 >= 0) ? *(const float4*)(features + (size_t)frow0 * D + st_kc * 4)
                             : make_float4(0.f, 0.f, 0.f, 0.f);
        pf[1] = (frow1 >= 0) ? *(const float4*)(features + (size_t)frow1 * D + st_kc * 4)
                             : make_float4(0.f, 0.f, 0.f, 0.f);
        pw[0] = *(const float4*)(wbase + (size_t)st_r * D + st_kc * 4);
        pw[1] = *(const float4*)(wbase + (size_t)(st_r + 32) * D + st_kc * 4);

        #pragma unroll
        for (int it = 0; it < 2; it++) {
            int s = st_r + it * 32;
            float vf[4] = {pf[it].x, pf[it].y, pf[it].z, pf[it].w};
            float vw[4] = {pw[it].x, pw[it].y, pw[it].z, pw[it].w};
            #pragma unroll
            for (int j = 0; j < 4; j++) {
                fsb[0 * (TK * 64) + idx64(st_kc * 4 + j, s)] = vf[j];
                wsb[0 * (TK * 64) + idx64(st_kc * 4 + j, s)] = vw[j];
            }
        }
        __syncthreads();

        for (int chunk = 0; chunk < NCH; chunk++) {
            int cur = chunk & 1;
            int nxt = cur ^ 1;
            if (chunk + 1 < NCH) {
                int k0 = (chunk + 1) * TK;
                pf[0] = (frow0 >= 0) ? *(const float4*)(features + (size_t)frow0 * D + k0 + st_kc * 4)
                                     : make_float4(0.f, 0.f, 0.f, 0.f);
                pf[1] = (frow1 >= 0) ? *(const float4*)(features + (size_t)frow1 * D + k0 + st_kc * 4)
                                     : make_float4(0.f, 0.f, 0.f, 0.f);
                pw[0] = *(const float4*)(wbase + (size_t)st_r * D + k0 + st_kc * 4);
                pw[1] = *(const float4*)(wbase + (size_t)(st_r + 32) * D + k0 + st_kc * 4);
            }

            const float* fsc = fsb + cur * (TK * 64);
            const float* wsc = wsb + cur * (TK * 64);
            #pragma unroll
            for (int kk = 0; kk < TK; kk++) {
                float4 fa = *(const float4*)&fsc[idx64v(kk, ty)];
                float4 wb = *(const float4*)&wsc[idx64v(kk, tx)];
                float f[4] = {fa.x, fa.y, fa.z, fa.w};
                float w[4] = {wb.x, wb.y, wb.z, wb.w};
                #pragma unroll
                for (int i = 0; i < 4; i++)
                    #pragma unroll
                    for (int j = 0; j < 4; j++)
                        acc[i][j] = fmaf(f[i], w[j], acc[i][j]);
            }

            if (chunk + 1 < NCH) {
                #pragma unroll
                for (int it = 0; it < 2; it++) {
                    int s = st_r + it * 32;
                    float vf[4] = {pf[it].x, pf[it].y, pf[it].z, pf[it].w};
                    float vw[4] = {pw[it].x, pw[it].y, pw[it].z, pw[it].w};
                    #pragma unroll
                    for (int j = 0; j < 4; j++) {
                        fsb[nxt * (TK * 64) + idx64(st_kc * 4 + j, s)] = vf[j];
                        wsb[nxt * (TK * 64) + idx64(st_kc * 4 + j, s)] = vw[j];
                    }
                }
                __syncthreads();
            }
        }

        // epilogue: bias + softmax + first-occurrence argmax (regs + 16-lane shfl)
        float4 b4 = *(const float4*)(eb + e * C + tx * 4);
        float bias[4] = {b4.x, b4.y, b4.z, b4.w};

        #pragma unroll
        for (int i = 0; i < 4; i++) {
            float v[4];
            #pragma unroll
            for (int j = 0; j < 4; j++) v[j] = acc[i][j] + bias[j];

            float mv = v[0]; int mi = tx * 4;
            #pragma unroll
            for (int j = 1; j < 4; j++)
                if (v[j] > mv) { mv = v[j]; mi = tx * 4 + j; }
            #pragma unroll
            for (int off = 1; off < 16; off <<= 1) {
                float ov = __shfl_xor_sync(0xffffffffu, mv, off);
                int   oi = __shfl_xor_sync(0xffffffffu, mi, off);
                if (ov > mv || (ov == mv && oi < mi)) { mv = ov; mi = oi; }
            }

            float sum = 0.f;
            #pragma unroll
            for (int j = 0; j < 4; j++) {
                v[j] = expf(v[j] - mv);
                sum += v[j];
            }
            #pragma unroll
            for (int off = 1; off < 16; off <<= 1)
                sum += __shfl_xor_sync(0xffffffffu, sum, off);
            float inv = 1.0f / sum;

            int row = ridx[ty * 4 + i];
            if (row >= 0) {
                float4 o = make_float4(v[0] * inv, v[1] * inv, v[2] * inv, v[3] * inv);
                *(float4*)(out_local + (size_t)row * C + tx * 4) = o;
                if (tx == 0)
                    out_global[row] = (float)(mi + e * C);
            }
        }
    }

    // =======================================================================
    // Reset persistent counters for the next graph replay.
    // =======================================================================
    __syncthreads();
    if (tid == 0) {
        unsigned d = atomicAdd(&g_done, 1u);
        if (d == GRID - 1) {
            #pragma unroll
            for (int i = 0; i < E; i++) g_counts[i] = 0;
            g_ticket = 0;
            g_bar = 0;
            __threadfence();
            g_done = 0;
        }
    }
}

// ---------------------------------------------------------------------------
// Output layout (reference tuple order, flattened+concatenated, fp32):
//   [0,              B*E)              coarse_output
//   [B*E,            B*E+B)            expert_id (as float)
//   [B*E+B,          B*E+B+B*C)        local_preds
//   [B*E+B+B*C,      B*E+2B+B*C)       global_preds
// ---------------------------------------------------------------------------
extern "C" void kernel_launch(void* const* d_in, const int* in_sizes, int n_in,
                              void* d_out, int out_size) {
    const float* features = (const float*)d_in[0];
    const float* cw       = (const float*)d_in[1];
    const float* cb       = (const float*)d_in[2];
    const float* ew       = (const float*)d_in[3];
    const float* eb       = (const float*)d_in[4];

    float* out        = (float*)d_out;
    float* out_coarse = out;
    float* out_eid    = out + (size_t)B * E;
    float* out_local  = out_eid + B;
    float* out_global = out_local + (size_t)B * C;

    moe_kernel<<<GRID, NTHREADS>>>(features, cw, cb, ew, eb,
                                   out_coarse, out_eid, out_local, out_global);
}

// round 13
// speedup vs baseline: 2.8521x; 1.3138x over previous
#include <cuda_runtime.h>
#include <cuda_bf16.h>
#include <math.h>

#define B 16384
#define D 2048
#define E 16
#define C 64

__device__ int g_counts[E];
__device__ int g_bucket[E * B];

__global__ void zero_counts_kernel() {
    if (threadIdx.x < E) g_counts[threadIdx.x] = 0;
}

// ======================= helpers ===========================================
__device__ __forceinline__ unsigned smem_u32(const void* p) {
    unsigned a;
    asm("{ .reg .u64 t; cvta.to.shared.u64 t, %1; cvt.u32.u64 %0, t; }" : "=r"(a) : "l"(p));
    return a;
}
// pack two f32 -> bf16x2 (first arg -> low half, second -> high half)
__device__ __forceinline__ unsigned pack2(float lo, float hi) {
    unsigned r; asm("cvt.rn.bf16x2.f32 %0, %1, %2;" : "=r"(r) : "f"(hi), "f"(lo)); return r;
}
__device__ __forceinline__ void sts128(unsigned a, unsigned x, unsigned y, unsigned z, unsigned w) {
    asm volatile("st.shared.v4.b32 [%0], {%1,%2,%3,%4};" :: "r"(a), "r"(x), "r"(y), "r"(z), "r"(w) : "memory");
}
__device__ __forceinline__ void ldsm4(unsigned addr, unsigned& r0, unsigned& r1, unsigned& r2, unsigned& r3) {
    asm volatile("ldmatrix.sync.aligned.m8n8.x4.shared.b16 {%0,%1,%2,%3}, [%4];"
        : "=r"(r0), "=r"(r1), "=r"(r2), "=r"(r3) : "r"(addr));
}
__device__ __forceinline__ void mma16816(float* c, const unsigned* a, unsigned b0, unsigned b1) {
    asm volatile("mma.sync.aligned.m16n8k16.row.col.f32.bf16.bf16.f32 "
        "{%0,%1,%2,%3}, {%4,%5,%6,%7}, {%8,%9}, {%0,%1,%2,%3};"
        : "+f"(c[0]), "+f"(c[1]), "+f"(c[2]), "+f"(c[3])
        : "r"(a[0]), "r"(a[1]), "r"(a[2]), "r"(a[3]), "r"(b0), "r"(b1));
}
// top-2 merge with first-occurrence tie-break
__device__ __forceinline__ void top2_merge(float& m1, int& c1, float& m2, int& c2,
                                           float om1, int oc1, float om2, int oc2) {
    if (om1 > m1 || (om1 == m1 && oc1 < c1)) {
        float nm2; int nc2;
        if (m1 > om2 || (m1 == om2 && c1 < oc2)) { nm2 = m1; nc2 = c1; }
        else { nm2 = om2; nc2 = oc2; }
        m1 = om1; c1 = oc1; m2 = nm2; c2 = nc2;
    } else if (om1 > m2 || (om1 == m2 && oc1 < c2)) {
        m2 = om1; c2 = oc1;
    }
}

// ======================= Kernel 1: coarse router (fp32, proven) ============
#define TK 32
#define NCH (D / TK)
__device__ __forceinline__ int idx64(int kr, int col) {
    return kr * 64 + (((col >> 2) ^ ((kr >> 2) & 7)) << 2) + (col & 3);
}
__device__ __forceinline__ int idx64v(int kr, int c4) { return kr * 64 + (((c4) ^ ((kr >> 2) & 7)) << 2); }
__device__ __forceinline__ int idx16(int kr, int col) {
    return kr * 16 + (((col >> 2) ^ ((kr >> 2) & 3)) << 2) + (col & 3);
}

__global__ __launch_bounds__(256) void coarse_kernel(
    const float* __restrict__ features, const float* __restrict__ cw,
    const float* __restrict__ cb, float* __restrict__ out_coarse, float* __restrict__ out_eid)
{
    __shared__ __align__(16) float fsb[2 * TK * 64];
    __shared__ __align__(16) float wsb[2 * TK * 16];

    int tid = threadIdx.x;
    int s0 = blockIdx.x * 64;
    int ty = tid >> 4, tx = tid & 15;
    int st_r = tid >> 3, st_kc = tid & 7;
    int w_e = tid >> 3, w_kc = tid & 7;

    float4 pf[2], pw;
    float acc[4] = {0.f, 0.f, 0.f, 0.f};

    pf[0] = *(const float4*)(features + (size_t)(s0 + st_r) * D + st_kc * 4);
    pf[1] = *(const float4*)(features + (size_t)(s0 + st_r + 32) * D + st_kc * 4);
    if (tid < 128) pw = *(const float4*)(cw + (size_t)w_e * D + w_kc * 4);

    #pragma unroll
    for (int it = 0; it < 2; it++) {
        int s = st_r + it * 32;
        float v[4] = {pf[it].x, pf[it].y, pf[it].z, pf[it].w};
        #pragma unroll
        for (int j = 0; j < 4; j++) fsb[idx64(st_kc * 4 + j, s)] = v[j];
    }
    if (tid < 128) {
        float v[4] = {pw.x, pw.y, pw.z, pw.w};
        #pragma unroll
        for (int j = 0; j < 4; j++) wsb[idx16(w_kc * 4 + j, w_e)] = v[j];
    }
    __syncthreads();

    for (int chunk = 0; chunk < NCH; chunk++) {
        int cur = chunk & 1, nxt = cur ^ 1;
        if (chunk + 1 < NCH) {
            int k0 = (chunk + 1) * TK;
            pf[0] = *(const float4*)(features + (size_t)(s0 + st_r) * D + k0 + st_kc * 4);
            pf[1] = *(const float4*)(features + (size_t)(s0 + st_r + 32) * D + k0 + st_kc * 4);
            if (tid < 128) pw = *(const float4*)(cw + (size_t)w_e * D + k0 + w_kc * 4);
        }
        const float* fsc = fsb + cur * (TK * 64);
        const float* wsc = wsb + cur * (TK * 16);
        #pragma unroll
        for (int kk = 0; kk < TK; kk++) {
            float4 fa = *(const float4*)&fsc[idx64v(kk, ty)];
            float w = wsc[idx16(kk, tx)];
            acc[0] = fmaf(fa.x, w, acc[0]);
            acc[1] = fmaf(fa.y, w, acc[1]);
            acc[2] = fmaf(fa.z, w, acc[2]);
            acc[3] = fmaf(fa.w, w, acc[3]);
        }
        if (chunk + 1 < NCH) {
            #pragma unroll
            for (int it = 0; it < 2; it++) {
                int s = st_r + it * 32;
                float v[4] = {pf[it].x, pf[it].y, pf[it].z, pf[it].w};
                #pragma unroll
                for (int j = 0; j < 4; j++) fsb[nxt * (TK * 64) + idx64(st_kc * 4 + j, s)] = v[j];
            }
            if (tid < 128) {
                float v[4] = {pw.x, pw.y, pw.z, pw.w};
                #pragma unroll
                for (int j = 0; j < 4; j++) wsb[nxt * (TK * 16) + idx16(w_kc * 4 + j, w_e)] = v[j];
            }
            __syncthreads();
        }
    }

    float bias = cb[tx];
    #pragma unroll
    for (int i = 0; i < 4; i++) {
        float v = acc[i] + bias;
        int gs = s0 + ty * 4 + i;
        out_coarse[(size_t)gs * E + tx] = v;
        float mv = v; int mi = tx;
        #pragma unroll
        for (int off = 1; off < 16; off <<= 1) {
            float ov = __shfl_xor_sync(0xffffffffu, mv, off);
            int   oi = __shfl_xor_sync(0xffffffffu, mi, off);
            if (ov > mv || (ov == mv && oi < mi)) { mv = ov; mi = oi; }
        }
        if (tx == 0) {
            out_eid[gs] = (float)mi;
            int pos = atomicAdd(&g_counts[mi], 1);
            g_bucket[mi * B + pos] = gs;
        }
    }
}

// ======================= Kernel 2: expert GEMM via mma.sync bf16 ===========
// Tile M=128 x N=64, 256 threads (8 warps, warp = 16-row strip x 64 cols).
// bf16 3-term split (hi*hi + hi*lo + lo*hi), fp32 accum. K-chunk 32, dbuf.
// smem rows padded to 80 B -> ldmatrix conflict-free.
#define RSB   80                  // bytes per smem row (32 bf16 + 8 pad)
#define BUFSZ 30720               // AHI 10240 | ALO 10240 | WHI 5120 | WLO 5120
#define O_ALO 10240
#define O_WHI 20480
#define O_WLO 25600
#define OFF_RIDX 61440
#define OFF_BIAS 61952
#define SMEM_TC  62208
#define NCHT (D / 32)             // 64

__global__ void __launch_bounds__(256, 2) expert_mma_kernel(
    const float* __restrict__ features, const float* __restrict__ ew,
    const float* __restrict__ eb, float* __restrict__ out_local,
    float* __restrict__ out_global)
{
    extern __shared__ __align__(16) char dsm[];
    int e = blockIdx.x, mt = blockIdx.y;
    int cnt = g_counts[e];
    int m0 = mt * 128;
    if (m0 >= cnt) return;

    unsigned sb = smem_u32(dsm);
    int tid = threadIdx.x, wid = tid >> 5, lid = tid & 31;

    if (tid < 128) {
        int r = m0 + tid;
        ((int*)(dsm + OFF_RIDX))[tid] = (r < cnt) ? g_bucket[e * B + r] : -1;
    }
    if (tid < C) ((float*)(dsm + OFF_BIAS))[tid] = eb[e * C + tid];
    __syncthreads();

    const int* ridx = (const int*)(dsm + OFF_RIDX);
    const float* bias = (const float*)(dsm + OFF_BIAS);
    const float* wbase = ew + (size_t)e * C * D;

    // staging mapping: A tasks (row 0..127, g8 0..3) = tid, tid+256; W task = tid
    int a_row0 = tid >> 2;            // 0..63
    int a_g8   = tid & 3;
    int frowA0 = ridx[a_row0];
    int frowA1 = ridx[a_row0 + 64];
    int w_row  = tid >> 2;            // 0..63
    int w_g8   = tid & 3;

    // ldmatrix lane-static offsets
    unsigned aoff = (unsigned)((wid * 16 + (lid & 15)) * RSB + (lid >> 4) * 16);
    unsigned boff = (unsigned)((((lid >> 4) * 8 + (lid & 7)) * RSB) + (((lid >> 3) & 1) * 16));

    float c[8][4];
    #pragma unroll
    for (int nb = 0; nb < 8; nb++)
        #pragma unroll
        for (int j = 0; j < 4; j++) c[nb][j] = 0.f;

    float4 pfa[2][2], pfw[2];

    // ---- prologue: load + stage chunk 0 ----
    {
        pfa[0][0] = (frowA0 >= 0) ? *(const float4*)(features + (size_t)frowA0 * D + a_g8 * 8)
                                  : make_float4(0.f, 0.f, 0.f, 0.f);
        pfa[0][1] = (frowA0 >= 0) ? *(const float4*)(features + (size_t)frowA0 * D + a_g8 * 8 + 4)
                                  : make_float4(0.f, 0.f, 0.f, 0.f);
        pfa[1][0] = (frowA1 >= 0) ? *(const float4*)(features + (size_t)frowA1 * D + a_g8 * 8)
                                  : make_float4(0.f, 0.f, 0.f, 0.f);
        pfa[1][1] = (frowA1 >= 0) ? *(const float4*)(features + (size_t)frowA1 * D + a_g8 * 8 + 4)
                                  : make_float4(0.f, 0.f, 0.f, 0.f);
        pfw[0] = *(const float4*)(wbase + (size_t)w_row * D + w_g8 * 8);
        pfw[1] = *(const float4*)(wbase + (size_t)w_row * D + w_g8 * 8 + 4);
    }

    #pragma unroll 1
    for (int ch = 0; ch < NCHT; ch++) {
        int cur = ch & 1, nxt = cur ^ 1;
        unsigned bbS = sb + (unsigned)(nxt * BUFSZ);   // staging target

        // stage prefetched data of chunk ch into buffer cur? No: chunk ch data was
        // staged last iteration. This iteration: (1) store prefetched chunk ch data
        // happens BEFORE loop for ch==0 handled in prologue... Unified scheme:
        // at loop top, regs hold chunk ch data; store into cur buffer, sync, then
        // prefetch ch+1 and compute on cur.
        {
            unsigned bbC = sb + (unsigned)(cur * BUFSZ);
            #pragma unroll
            for (int it = 0; it < 2; it++) {
                int row = a_row0 + it * 64;
                float f[8] = {pfa[it][0].x, pfa[it][0].y, pfa[it][0].z, pfa[it][0].w,
                              pfa[it][1].x, pfa[it][1].y, pfa[it][1].z, pfa[it][1].w};
                unsigned h[4], l[4];
                #pragma unroll
                for (int i = 0; i < 4; i++) {
                    float h0 = __bfloat162float(__float2bfloat16(f[2*i]));
                    float h1 = __bfloat162float(__float2bfloat16(f[2*i+1]));
                    h[i] = pack2(h0, h1);
                    l[i] = pack2(f[2*i] - h0, f[2*i+1] - h1);
                }
                unsigned o = (unsigned)(row * RSB + a_g8 * 16);
                sts128(bbC + o, h[0], h[1], h[2], h[3]);
                sts128(bbC + O_ALO + o, l[0], l[1], l[2], l[3]);
            }
            {
                float f[8] = {pfw[0].x, pfw[0].y, pfw[0].z, pfw[0].w,
                              pfw[1].x, pfw[1].y, pfw[1].z, pfw[1].w};
                unsigned h[4], l[4];
                #pragma unroll
                for (int i = 0; i < 4; i++) {
                    float h0 = __bfloat162float(__float2bfloat16(f[2*i]));
                    float h1 = __bfloat162float(__float2bfloat16(f[2*i+1]));
                    h[i] = pack2(h0, h1);
                    l[i] = pack2(f[2*i] - h0, f[2*i+1] - h1);
                }
                unsigned o = (unsigned)(w_row * RSB + w_g8 * 16);
                sts128(bbC + O_WHI + o, h[0], h[1], h[2], h[3]);
                sts128(bbC + O_WLO + o, l[0], l[1], l[2], l[3]);
            }
        }
        __syncthreads();

        // prefetch chunk ch+1
        if (ch + 1 < NCHT) {
            int k0 = (ch + 1) * 32;
            pfa[0][0] = (frowA0 >= 0) ? *(const float4*)(features + (size_t)frowA0 * D + k0 + a_g8 * 8)
                                      : make_float4(0.f, 0.f, 0.f, 0.f);
            pfa[0][1] = (frowA0 >= 0) ? *(const float4*)(features + (size_t)frowA0 * D + k0 + a_g8 * 8 + 4)
                                      : make_float4(0.f, 0.f, 0.f, 0.f);
            pfa[1][0] = (frowA1 >= 0) ? *(const float4*)(features + (size_t)frowA1 * D + k0 + a_g8 * 8)
                                      : make_float4(0.f, 0.f, 0.f, 0.f);
            pfa[1][1] = (frowA1 >= 0) ? *(const float4*)(features + (size_t)frowA1 * D + k0 + a_g8 * 8 + 4)
                                      : make_float4(0.f, 0.f, 0.f, 0.f);
            pfw[0] = *(const float4*)(wbase + (size_t)w_row * D + k0 + w_g8 * 8);
            pfw[1] = *(const float4*)(wbase + (size_t)w_row * D + k0 + w_g8 * 8 + 4);
        }

        // compute on buffer cur
        unsigned bb = sb + (unsigned)(cur * BUFSZ);
        #pragma unroll
        for (int s = 0; s < 2; s++) {
            unsigned ahi[4], alo[4];
            ldsm4(bb + aoff + s * 32, ahi[0], ahi[1], ahi[2], ahi[3]);
            ldsm4(bb + O_ALO + aoff + s * 32, alo[0], alo[1], alo[2], alo[3]);
            #pragma unroll
            for (int nbp = 0; nbp < 4; nbp++) {
                unsigned bh[4], bl[4];
                unsigned bo = boff + (unsigned)(nbp * 16 * RSB) + s * 32;
                ldsm4(bb + O_WHI + bo, bh[0], bh[1], bh[2], bh[3]);
                ldsm4(bb + O_WLO + bo, bl[0], bl[1], bl[2], bl[3]);
                mma16816(c[2*nbp],     ahi, bh[0], bh[1]);
                mma16816(c[2*nbp],     ahi, bl[0], bl[1]);
                mma16816(c[2*nbp],     alo, bh[0], bh[1]);
                mma16816(c[2*nbp + 1], ahi, bh[2], bh[3]);
                mma16816(c[2*nbp + 1], ahi, bl[2], bl[3]);
                mma16816(c[2*nbp + 1], alo, bh[2], bh[3]);
            }
        }
        __syncthreads();   // everyone done reading cur before it's re-staged
    }

    // ---- epilogue ----
    int qm = lid & 3;                 // quad lane
    int rb = lid >> 2;                // fragment row 0..7
    // add bias in place
    #pragma unroll
    for (int nb = 0; nb < 8; nb++) {
        float b0 = bias[nb * 8 + 2 * qm];
        float b1 = bias[nb * 8 + 2 * qm + 1];
        c[nb][0] += b0; c[nb][1] += b1;
        c[nb][2] += b0; c[nb][3] += b1;
    }

    #pragma unroll
    for (int half = 0; half < 2; half++) {
        int row  = wid * 16 + rb + half * 8;
        int frow = ridx[row];
        int j0 = half * 2;

        // local top-2 (ascending col order for first-occurrence ties)
        float m1 = -3.4e38f, m2 = -3.4e38f; int c1 = 0, c2 = 0;
        #pragma unroll
        for (int nb = 0; nb < 8; nb++) {
            #pragma unroll
            for (int j = 0; j < 2; j++) {
                float v = c[nb][j0 + j];
                int col = nb * 8 + 2 * qm + j;
                if (v > m1 || (v == m1 && col < c1)) { m2 = m1; c2 = c1; m1 = v; c1 = col; }
                else if (v > m2 || (v == m2 && col < c2)) { m2 = v; c2 = col; }
            }
        }
        #pragma unroll
        for (int off = 1; off < 4; off <<= 1) {
            float om1 = __shfl_xor_sync(0xffffffffu, m1, off);
            int   oc1 = __shfl_xor_sync(0xffffffffu, c1, off);
            float om2 = __shfl_xor_sync(0xffffffffu, m2, off);
            int   oc2 = __shfl_xor_sync(0xffffffffu, c2, off);
            top2_merge(m1, c1, m2, c2, om1, oc1, om2, oc2);
        }

        int win = c1;
        if (frow >= 0 && (m1 - m2) < 2e-4f) {
            // exact fp32 recompute of both candidates, quad-cooperative
            const float* fr = features + (size_t)frow * D;
            const float* w1 = wbase + (size_t)c1 * D;
            const float* w2 = wbase + (size_t)c2 * D;
            float s1 = 0.f, s2 = 0.f;
            for (int k = qm * 4; k < D; k += 16) {
                float4 f = *(const float4*)(fr + k);
                float4 a = *(const float4*)(w1 + k);
                float4 b = *(const float4*)(w2 + k);
                s1 = fmaf(f.x, a.x, fmaf(f.y, a.y, fmaf(f.z, a.z, fmaf(f.w, a.w, s1))));
                s2 = fmaf(f.x, b.x, fmaf(f.y, b.y, fmaf(f.z, b.z, fmaf(f.w, b.w, s2))));
            }
            #pragma unroll
            for (int off = 1; off < 4; off <<= 1) {
                s1 += __shfl_xor_sync(0xffffffffu, s1, off);
                s2 += __shfl_xor_sync(0xffffffffu, s2, off);
            }
            s1 += bias[c1]; s2 += bias[c2];
            if (s2 > s1 || (s2 == s1 && c2 < c1)) win = c2;
        }

        // softmax over this row (16 values per lane, quad-reduced sum)
        float sum = 0.f;
        float ev[16];
        #pragma unroll
        for (int nb = 0; nb < 8; nb++) {
            #pragma unroll
            for (int j = 0; j < 2; j++) {
                float v = expf(c[nb][j0 + j] - m1);
                ev[nb * 2 + j] = v;
                sum += v;
            }
        }
        #pragma unroll
        for (int off = 1; off < 4; off <<= 1)
            sum += __shfl_xor_sync(0xffffffffu, sum, off);
        float inv = 1.0f / sum;

        if (frow >= 0) {
            float* dst = out_local + (size_t)frow * C;
            #pragma unroll
            for (int nb = 0; nb < 8; nb++) {
                float2 o = make_float2(ev[nb * 2] * inv, ev[nb * 2 + 1] * inv);
                *(float2*)(dst + nb * 8 + 2 * qm) = o;
            }
            if (qm == 0)
                out_global[frow] = (float)(win + e * C);
        }
    }
}

// ===========================================================================
// Output layout: coarse [B*E] | expert_id [B] | local_preds [B*C] | global [B]
// ===========================================================================
extern "C" void kernel_launch(void* const* d_in, const int* in_sizes, int n_in,
                              void* d_out, int out_size) {
    const float* features = (const float*)d_in[0];
    const float* cw       = (const float*)d_in[1];
    const float* cb       = (const float*)d_in[2];
    const float* ew       = (const float*)d_in[3];
    const float* eb       = (const float*)d_in[4];

    float* out        = (float*)d_out;
    float* out_coarse = out;
    float* out_eid    = out + (size_t)B * E;
    float* out_local  = out_eid + B;
    float* out_global = out_local + (size_t)B * C;

    cudaFuncSetAttribute(expert_mma_kernel, cudaFuncAttributeMaxDynamicSharedMemorySize, SMEM_TC);

    zero_counts_kernel<<<1, 32>>>();
    coarse_kernel<<<B / 64, 256>>>(features, cw, cb, out_coarse, out_eid);
    dim3 g2(E, 16);   // covers cnt_e <= 2048 (mean 1024)
    expert_mma_kernel<<<g2, 256, SMEM_TC>>>(features, ew, eb, out_local, out_global);
}

// round 15
// speedup vs baseline: 3.0403x; 1.0660x over previous
#include <cuda_runtime.h>
#include <cuda_bf16.h>
#include <math.h>

#define B 16384
#define D 2048
#define E 16
#define C 64

__device__ int g_counts[E];
__device__ int g_bucket[E * B];

__global__ void zero_counts_kernel() {
    if (threadIdx.x < E) g_counts[threadIdx.x] = 0;
}

// ======================= helpers ===========================================
__device__ __forceinline__ unsigned smem_u32(const void* p) {
    unsigned a;
    asm("{ .reg .u64 t; cvta.to.shared.u64 t, %1; cvt.u32.u64 %0, t; }" : "=r"(a) : "l"(p));
    return a;
}
__device__ __forceinline__ unsigned pack2(float lo, float hi) {
    unsigned r; asm("cvt.rn.bf16x2.f32 %0, %1, %2;" : "=r"(r) : "f"(hi), "f"(lo)); return r;
}
__device__ __forceinline__ void sts128(unsigned a, unsigned x, unsigned y, unsigned z, unsigned w) {
    asm volatile("st.shared.v4.b32 [%0], {%1,%2,%3,%4};" :: "r"(a), "r"(x), "r"(y), "r"(z), "r"(w) : "memory");
}
__device__ __forceinline__ void ldsm4(unsigned addr, unsigned& r0, unsigned& r1, unsigned& r2, unsigned& r3) {
    asm volatile("ldmatrix.sync.aligned.m8n8.x4.shared.b16 {%0,%1,%2,%3}, [%4];"
        : "=r"(r0), "=r"(r1), "=r"(r2), "=r"(r3) : "r"(addr));
}
__device__ __forceinline__ void mma16816(float* c, const unsigned* a, unsigned b0, unsigned b1) {
    asm volatile("mma.sync.aligned.m16n8k16.row.col.f32.bf16.bf16.f32 "
        "{%0,%1,%2,%3}, {%4,%5,%6,%7}, {%8,%9}, {%0,%1,%2,%3};"
        : "+f"(c[0]), "+f"(c[1]), "+f"(c[2]), "+f"(c[3])
        : "r"(a[0]), "r"(a[1]), "r"(a[2]), "r"(a[3]), "r"(b0), "r"(b1));
}
__device__ __forceinline__ void top2_merge(float& m1, int& c1, float& m2, int& c2,
                                           float om1, int oc1, float om2, int oc2) {
    if (om1 > m1 || (om1 == m1 && oc1 < c1)) {
        float nm2; int nc2;
        if (m1 > om2 || (m1 == om2 && c1 < oc2)) { nm2 = m1; nc2 = c1; }
        else { nm2 = om2; nc2 = oc2; }
        m1 = om1; c1 = oc1; m2 = nm2; c2 = nc2;
    } else if (om1 > m2 || (om1 == m2 && oc1 < c2)) {
        m2 = om1; c2 = oc1;
    }
}

// ======================= Kernel 1: coarse router (fp32, proven) ============
#define TK 32
#define NCH (D / TK)
__device__ __forceinline__ int idx64(int kr, int col) {
    return kr * 64 + (((col >> 2) ^ ((kr >> 2) & 7)) << 2) + (col & 3);
}
__device__ __forceinline__ int idx64v(int kr, int c4) { return kr * 64 + (((c4) ^ ((kr >> 2) & 7)) << 2); }
__device__ __forceinline__ int idx16(int kr, int col) {
    return kr * 16 + (((col >> 2) ^ ((kr >> 2) & 3)) << 2) + (col & 3);
}

__global__ __launch_bounds__(256) void coarse_kernel(
    const float* __restrict__ features, const float* __restrict__ cw,
    const float* __restrict__ cb, float* __restrict__ out_coarse, float* __restrict__ out_eid)
{
    __shared__ __align__(16) float fsb[2 * TK * 64];
    __shared__ __align__(16) float wsb[2 * TK * 16];

    int tid = threadIdx.x;
    int s0 = blockIdx.x * 64;
    int ty = tid >> 4, tx = tid & 15;
    int st_r = tid >> 3, st_kc = tid & 7;
    int w_e = tid >> 3, w_kc = tid & 7;

    float4 pf[2], pw;
    float acc[4] = {0.f, 0.f, 0.f, 0.f};

    pf[0] = *(const float4*)(features + (size_t)(s0 + st_r) * D + st_kc * 4);
    pf[1] = *(const float4*)(features + (size_t)(s0 + st_r + 32) * D + st_kc * 4);
    if (tid < 128) pw = *(const float4*)(cw + (size_t)w_e * D + w_kc * 4);

    #pragma unroll
    for (int it = 0; it < 2; it++) {
        int s = st_r + it * 32;
        float v[4] = {pf[it].x, pf[it].y, pf[it].z, pf[it].w};
        #pragma unroll
        for (int j = 0; j < 4; j++) fsb[idx64(st_kc * 4 + j, s)] = v[j];
    }
    if (tid < 128) {
        float v[4] = {pw.x, pw.y, pw.z, pw.w};
        #pragma unroll
        for (int j = 0; j < 4; j++) wsb[idx16(w_kc * 4 + j, w_e)] = v[j];
    }
    __syncthreads();

    for (int chunk = 0; chunk < NCH; chunk++) {
        int cur = chunk & 1, nxt = cur ^ 1;
        if (chunk + 1 < NCH) {
            int k0 = (chunk + 1) * TK;
            pf[0] = *(const float4*)(features + (size_t)(s0 + st_r) * D + k0 + st_kc * 4);
            pf[1] = *(const float4*)(features + (size_t)(s0 + st_r + 32) * D + k0 + st_kc * 4);
            if (tid < 128) pw = *(const float4*)(cw + (size_t)w_e * D + k0 + w_kc * 4);
        }
        const float* fsc = fsb + cur * (TK * 64);
        const float* wsc = wsb + cur * (TK * 16);
        #pragma unroll
        for (int kk = 0; kk < TK; kk++) {
            float4 fa = *(const float4*)&fsc[idx64v(kk, ty)];
            float w = wsc[idx16(kk, tx)];
            acc[0] = fmaf(fa.x, w, acc[0]);
            acc[1] = fmaf(fa.y, w, acc[1]);
            acc[2] = fmaf(fa.z, w, acc[2]);
            acc[3] = fmaf(fa.w, w, acc[3]);
        }
        if (chunk + 1 < NCH) {
            #pragma unroll
            for (int it = 0; it < 2; it++) {
                int s = st_r + it * 32;
                float v[4] = {pf[it].x, pf[it].y, pf[it].z, pf[it].w};
                #pragma unroll
                for (int j = 0; j < 4; j++) fsb[nxt * (TK * 64) + idx64(st_kc * 4 + j, s)] = v[j];
            }
            if (tid < 128) {
                float v[4] = {pw.x, pw.y, pw.z, pw.w};
                #pragma unroll
                for (int j = 0; j < 4; j++) wsb[nxt * (TK * 16) + idx16(w_kc * 4 + j, w_e)] = v[j];
            }
            __syncthreads();
        }
    }

    float bias = cb[tx];
    #pragma unroll
    for (int i = 0; i < 4; i++) {
        float v = acc[i] + bias;
        int gs = s0 + ty * 4 + i;
        out_coarse[(size_t)gs * E + tx] = v;
        float mv = v; int mi = tx;
        #pragma unroll
        for (int off = 1; off < 16; off <<= 1) {
            float ov = __shfl_xor_sync(0xffffffffu, mv, off);
            int   oi = __shfl_xor_sync(0xffffffffu, mi, off);
            if (ov > mv || (ov == mv && oi < mi)) { mv = ov; mi = oi; }
        }
        if (tx == 0) {
            out_eid[gs] = (float)mi;
            int pos = atomicAdd(&g_counts[mi], 1);
            g_bucket[mi * B + pos] = gs;
        }
    }
}

// ======================= Kernel 2: expert GEMM via mma.sync bf16 ===========
// Tile M=64 x N=64, 128 threads (4 warps, warp = 16-row strip x 64 cols).
// bf16 3-term split, fp32 accum, K-chunk 32, dbuf. Rows padded to 80B.
// Grid (E, 32): ~272 working blocks -> ~2 co-resident per SM (vs 1 in R13).
#define RSB   80
#define BUFSZ 20480               // AHI 5120 | ALO 5120 | WHI 5120 | WLO 5120
#define O_ALO 5120
#define O_WHI 10240
#define O_WLO 15360
#define OFF_RIDX 40960            // 2*BUFSZ
#define OFF_BIAS 41216
#define SMEM_TC  41472
#define NCHT (D / 32)             // 64
#define MT_MAX 32                 // covers cnt_e <= 2048

__global__ void __launch_bounds__(128, 4) expert_mma_kernel(
    const float* __restrict__ features, const float* __restrict__ ew,
    const float* __restrict__ eb, float* __restrict__ out_local,
    float* __restrict__ out_global)
{
    extern __shared__ __align__(16) char dsm[];
    int e = blockIdx.x, mt = blockIdx.y;
    int cnt = g_counts[e];
    int m0 = mt * 64;
    if (m0 >= cnt) return;

    unsigned sb = smem_u32(dsm);
    int tid = threadIdx.x, wid = tid >> 5, lid = tid & 31;

    if (tid < 64) {
        int r = m0 + tid;
        ((int*)(dsm + OFF_RIDX))[tid] = (r < cnt) ? g_bucket[e * B + r] : -1;
        ((float*)(dsm + OFF_BIAS))[tid] = eb[e * C + tid];
    }
    __syncthreads();

    const int* ridx = (const int*)(dsm + OFF_RIDX);
    const float* bias = (const float*)(dsm + OFF_BIAS);
    const float* wbase = ew + (size_t)e * C * D;

    // staging: A 64 rows x 4 g8 = 256 tasks (2/thread); W same
    int s_row = tid >> 2;            // 0..31; tasks add it*32
    int s_g8  = tid & 3;
    int frow0 = ridx[s_row];
    int frow1 = ridx[s_row + 32];

    unsigned aoff = (unsigned)((wid * 16 + (lid & 15)) * RSB + (lid >> 4) * 16);
    unsigned boff = (unsigned)((((lid >> 4) * 8 + (lid & 7)) * RSB) + (((lid >> 3) & 1) * 16));

    float c[8][4];
    #pragma unroll
    for (int nb = 0; nb < 8; nb++)
        #pragma unroll
        for (int j = 0; j < 4; j++) c[nb][j] = 0.f;

    float4 pfa[2][2], pfw[2][2];

    // prologue: chunk 0 loads
    pfa[0][0] = (frow0 >= 0) ? *(const float4*)(features + (size_t)frow0 * D + s_g8 * 8)
                             : make_float4(0.f, 0.f, 0.f, 0.f);
    pfa[0][1] = (frow0 >= 0) ? *(const float4*)(features + (size_t)frow0 * D + s_g8 * 8 + 4)
                             : make_float4(0.f, 0.f, 0.f, 0.f);
    pfa[1][0] = (frow1 >= 0) ? *(const float4*)(features + (size_t)frow1 * D + s_g8 * 8)
                             : make_float4(0.f, 0.f, 0.f, 0.f);
    pfa[1][1] = (frow1 >= 0) ? *(const float4*)(features + (size_t)frow1 * D + s_g8 * 8 + 4)
                             : make_float4(0.f, 0.f, 0.f, 0.f);
    pfw[0][0] = *(const float4*)(wbase + (size_t)s_row * D + s_g8 * 8);
    pfw[0][1] = *(const float4*)(wbase + (size_t)s_row * D + s_g8 * 8 + 4);
    pfw[1][0] = *(const float4*)(wbase + (size_t)(s_row + 32) * D + s_g8 * 8);
    pfw[1][1] = *(const float4*)(wbase + (size_t)(s_row + 32) * D + s_g8 * 8 + 4);

    #pragma unroll 1
    for (int ch = 0; ch < NCHT; ch++) {
        int cur = ch & 1;
        unsigned bbC = sb + (unsigned)(cur * BUFSZ);

        // stage chunk ch (in regs) into buffer cur
        #pragma unroll
        for (int it = 0; it < 2; it++) {
            int row = s_row + it * 32;
            unsigned o = (unsigned)(row * RSB + s_g8 * 16);
            {
                float f[8] = {pfa[it][0].x, pfa[it][0].y, pfa[it][0].z, pfa[it][0].w,
                              pfa[it][1].x, pfa[it][1].y, pfa[it][1].z, pfa[it][1].w};
                unsigned h[4], l[4];
                #pragma unroll
                for (int i = 0; i < 4; i++) {
                    float h0 = __bfloat162float(__float2bfloat16(f[2*i]));
                    float h1 = __bfloat162float(__float2bfloat16(f[2*i+1]));
                    h[i] = pack2(h0, h1);
                    l[i] = pack2(f[2*i] - h0, f[2*i+1] - h1);
                }
                sts128(bbC + o, h[0], h[1], h[2], h[3]);
                sts128(bbC + O_ALO + o, l[0], l[1], l[2], l[3]);
            }
            {
                float f[8] = {pfw[it][0].x, pfw[it][0].y, pfw[it][0].z, pfw[it][0].w,
                              pfw[it][1].x, pfw[it][1].y, pfw[it][1].z, pfw[it][1].w};
                unsigned h[4], l[4];
                #pragma unroll
                for (int i = 0; i < 4; i++) {
                    float h0 = __bfloat162float(__float2bfloat16(f[2*i]));
                    float h1 = __bfloat162float(__float2bfloat16(f[2*i+1]));
                    h[i] = pack2(h0, h1);
                    l[i] = pack2(f[2*i] - h0, f[2*i+1] - h1);
                }
                sts128(bbC + O_WHI + o, h[0], h[1], h[2], h[3]);
                sts128(bbC + O_WLO + o, l[0], l[1], l[2], l[3]);
            }
        }
        __syncthreads();

        // prefetch chunk ch+1
        if (ch + 1 < NCHT) {
            int k0 = (ch + 1) * 32;
            pfa[0][0] = (frow0 >= 0) ? *(const float4*)(features + (size_t)frow0 * D + k0 + s_g8 * 8)
                                     : make_float4(0.f, 0.f, 0.f, 0.f);
            pfa[0][1] = (frow0 >= 0) ? *(const float4*)(features + (size_t)frow0 * D + k0 + s_g8 * 8 + 4)
                                     : make_float4(0.f, 0.f, 0.f, 0.f);
            pfa[1][0] = (frow1 >= 0) ? *(const float4*)(features + (size_t)frow1 * D + k0 + s_g8 * 8)
                                     : make_float4(0.f, 0.f, 0.f, 0.f);
            pfa[1][1] = (frow1 >= 0) ? *(const float4*)(features + (size_t)frow1 * D + k0 + s_g8 * 8 + 4)
                                     : make_float4(0.f, 0.f, 0.f, 0.f);
            pfw[0][0] = *(const float4*)(wbase + (size_t)s_row * D + k0 + s_g8 * 8);
            pfw[0][1] = *(const float4*)(wbase + (size_t)s_row * D + k0 + s_g8 * 8 + 4);
            pfw[1][0] = *(const float4*)(wbase + (size_t)(s_row + 32) * D + k0 + s_g8 * 8);
            pfw[1][1] = *(const float4*)(wbase + (size_t)(s_row + 32) * D + k0 + s_g8 * 8 + 4);
        }

        // compute on buffer cur
        #pragma unroll
        for (int s = 0; s < 2; s++) {
            unsigned ahi[4], alo[4];
            ldsm4(bbC + aoff + s * 32, ahi[0], ahi[1], ahi[2], ahi[3]);
            ldsm4(bbC + O_ALO + aoff + s * 32, alo[0], alo[1], alo[2], alo[3]);
            #pragma unroll
            for (int nbp = 0; nbp < 4; nbp++) {
                unsigned bh[4], bl[4];
                unsigned bo = boff + (unsigned)(nbp * 16 * RSB) + s * 32;
                ldsm4(bbC + O_WHI + bo, bh[0], bh[1], bh[2], bh[3]);
                ldsm4(bbC + O_WLO + bo, bl[0], bl[1], bl[2], bl[3]);
                mma16816(c[2*nbp],     ahi, bh[0], bh[1]);
                mma16816(c[2*nbp],     ahi, bl[0], bl[1]);
                mma16816(c[2*nbp],     alo, bh[0], bh[1]);
                mma16816(c[2*nbp + 1], ahi, bh[2], bh[3]);
                mma16816(c[2*nbp + 1], ahi, bl[2], bl[3]);
                mma16816(c[2*nbp + 1], alo, bh[2], bh[3]);
            }
        }
        __syncthreads();
    }

    // ---- epilogue (verbatim R13; 4 warps cover 64 rows) ----
    int qm = lid & 3, rb = lid >> 2;
    #pragma unroll
    for (int nb = 0; nb < 8; nb++) {
        float b0 = bias[nb * 8 + 2 * qm];
        float b1 = bias[nb * 8 + 2 * qm + 1];
        c[nb][0] += b0; c[nb][1] += b1;
        c[nb][2] += b0; c[nb][3] += b1;
    }

    #pragma unroll
    for (int half = 0; half < 2; half++) {
        int row  = wid * 16 + rb + half * 8;
        int frow = ridx[row];
        int j0 = half * 2;

        float m1 = -3.4e38f, m2 = -3.4e38f; int c1 = 0, c2 = 0;
        #pragma unroll
        for (int nb = 0; nb < 8; nb++) {
            #pragma unroll
            for (int j = 0; j < 2; j++) {
                float v = c[nb][j0 + j];
                int col = nb * 8 + 2 * qm + j;
                if (v > m1 || (v == m1 && col < c1)) { m2 = m1; c2 = c1; m1 = v; c1 = col; }
                else if (v > m2 || (v == m2 && col < c2)) { m2 = v; c2 = col; }
            }
        }
        #pragma unroll
        for (int off = 1; off < 4; off <<= 1) {
            float om1 = __shfl_xor_sync(0xffffffffu, m1, off);
            int   oc1 = __shfl_xor_sync(0xffffffffu, c1, off);
            float om2 = __shfl_xor_sync(0xffffffffu, m2, off);
            int   oc2 = __shfl_xor_sync(0xffffffffu, c2, off);
            top2_merge(m1, c1, m2, c2, om1, oc1, om2, oc2);
        }

        int win = c1;
        if (frow >= 0 && (m1 - m2) < 2e-4f) {
            const float* fr = features + (size_t)frow * D;
            const float* w1 = wbase + (size_t)c1 * D;
            const float* w2 = wbase + (size_t)c2 * D;
            float s1 = 0.f, s2 = 0.f;
            for (int k = qm * 4; k < D; k += 16) {
                float4 f = *(const float4*)(fr + k);
                float4 a = *(const float4*)(w1 + k);
                float4 b = *(const float4*)(w2 + k);
                s1 = fmaf(f.x, a.x, fmaf(f.y, a.y, fmaf(f.z, a.z, fmaf(f.w, a.w, s1))));
                s2 = fmaf(f.x, b.x, fmaf(f.y, b.y, fmaf(f.z, b.z, fmaf(f.w, b.w, s2))));
            }
            #pragma unroll
            for (int off = 1; off < 4; off <<= 1) {
                s1 += __shfl_xor_sync(0xffffffffu, s1, off);
                s2 += __shfl_xor_sync(0xffffffffu, s2, off);
            }
            s1 += bias[c1]; s2 += bias[c2];
            if (s2 > s1 || (s2 == s1 && c2 < c1)) win = c2;
        }

        float sum = 0.f;
        float ev[16];
        #pragma unroll
        for (int nb = 0; nb < 8; nb++) {
            #pragma unroll
            for (int j = 0; j < 2; j++) {
                float v = expf(c[nb][j0 + j] - m1);
                ev[nb * 2 + j] = v;
                sum += v;
            }
        }
        #pragma unroll
        for (int off = 1; off < 4; off <<= 1)
            sum += __shfl_xor_sync(0xffffffffu, sum, off);
        float inv = 1.0f / sum;

        if (frow >= 0) {
            float* dst = out_local + (size_t)frow * C;
            #pragma unroll
            for (int nb = 0; nb < 8; nb++) {
                float2 o = make_float2(ev[nb * 2] * inv, ev[nb * 2 + 1] * inv);
                *(float2*)(dst + nb * 8 + 2 * qm) = o;
            }
            if (qm == 0)
                out_global[frow] = (float)(win + e * C);
        }
    }
}

// ===========================================================================
// Output layout: coarse [B*E] | expert_id [B] | local_preds [B*C] | global [B]
// ===========================================================================
extern "C" void kernel_launch(void* const* d_in, const int* in_sizes, int n_in,
                              void* d_out, int out_size) {
    const float* features = (const float*)d_in[0];
    const float* cw       = (const float*)d_in[1];
    const float* cb       = (const float*)d_in[2];
    const float* ew       = (const float*)d_in[3];
    const float* eb       = (const float*)d_in[4];

    float* out        = (float*)d_out;
    float* out_coarse = out;
    float* out_eid    = out + (size_t)B * E;
    float* out_local  = out_eid + B;
    float* out_global = out_local + (size_t)B * C;

    static int attr_set = 0;
    if (!attr_set) {
        cudaFuncSetAttribute(expert_mma_kernel, cudaFuncAttributeMaxDynamicSharedMemorySize, SMEM_TC);
        attr_set = 1;
    }

    zero_counts_kernel<<<1, 32>>>();
    coarse_kernel<<<B / 64, 256>>>(features, cw, cb, out_coarse, out_eid);
    dim3 g2(E, MT_MAX);   // covers cnt_e <= 2048 (mean 1024)
    expert_mma_kernel<<<g2, 128, SMEM_TC>>>(features, ew, eb, out_local, out_global);
}